// round 1
// baseline (speedup 1.0000x reference)
#include <cuda_runtime.h>
#include <math.h>

#define W_LEN   1024
#define BSZ     16
#define EMBED   512
#define NHEADS  8
#define HEAD_DIM 64
#define M_ROWS  (W_LEN*BSZ)      /* 16384 */
#define QKV_N   (3*EMBED)        /* 1536  */

// Scratch (no-alloc rule: __device__ globals)
__device__ float g_xnorm[M_ROWS*EMBED];   // 32 MB
__device__ float g_qkv[M_ROWS*QKV_N];     // 100 MB
__device__ float g_attn[M_ROWS*EMBED];    // 32 MB

// ---------------------------------------------------------------- LayerNorm
__global__ void __launch_bounds__(256) ln_kernel(const float* __restrict__ feat,
                                                 const float* __restrict__ gam,
                                                 const float* __restrict__ bet) {
    int row = blockIdx.x;
    int t = threadIdx.x;                       // 256 threads, 2 floats each
    const float2 v = ((const float2*)(feat + (size_t)row * EMBED))[t];
    __shared__ float red[8];

    float s = v.x + v.y;
    #pragma unroll
    for (int o = 16; o; o >>= 1) s += __shfl_xor_sync(0xffffffffu, s, o);
    if ((t & 31) == 0) red[t >> 5] = s;
    __syncthreads();
    float tot = 0.f;
    #pragma unroll
    for (int i = 0; i < 8; i++) tot += red[i];
    float mu = tot * (1.f / EMBED);
    __syncthreads();

    float dx = v.x - mu, dy = v.y - mu;
    float s2 = dx * dx + dy * dy;
    #pragma unroll
    for (int o = 16; o; o >>= 1) s2 += __shfl_xor_sync(0xffffffffu, s2, o);
    if ((t & 31) == 0) red[t >> 5] = s2;
    __syncthreads();
    float var = 0.f;
    #pragma unroll
    for (int i = 0; i < 8; i++) var += red[i];
    float rstd = rsqrtf(var * (1.f / EMBED) + 1e-5f);

    float2 g2 = ((const float2*)gam)[t];
    float2 b2 = ((const float2*)bet)[t];
    float2 o;
    o.x = dx * rstd * g2.x + b2.x;
    o.y = dy * rstd * g2.y + b2.y;
    ((float2*)(g_xnorm + (size_t)row * EMBED))[t] = o;
}

// ------------------------------------------------------- SGEMM  C = A * B^T
// A [M,K] row-major (K contiguous), B [N,K] row-major (K contiguous).
// BM=BN=128, BK=16, 256 threads, 8x8 microtile. M from gridDim.y*128.
template <bool RESID>
__global__ void __launch_bounds__(256) sgemm_tn(const float* __restrict__ A,
                                                const float* __restrict__ B,
                                                const float* __restrict__ bias,
                                                const float* __restrict__ resid,
                                                float* __restrict__ C,
                                                int N, int K) {
    __shared__ __align__(16) float As[16][132];
    __shared__ __align__(16) float Bs[16][132];

    int tid = threadIdx.x;
    int m0 = blockIdx.y * 128, n0 = blockIdx.x * 128;
    int lr = tid >> 2;            // 0..63
    int lc = (tid & 3) * 4;       // 0,4,8,12
    int tx = tid & 15, ty = tid >> 4;

    float acc[8][8];
    #pragma unroll
    for (int i = 0; i < 8; i++)
        #pragma unroll
        for (int j = 0; j < 8; j++) acc[i][j] = 0.f;

    for (int k0 = 0; k0 < K; k0 += 16) {
        #pragma unroll
        for (int rr = 0; rr < 128; rr += 64) {
            float4 a = *(const float4*)&A[(size_t)(m0 + lr + rr) * K + k0 + lc];
            As[lc + 0][lr + rr] = a.x; As[lc + 1][lr + rr] = a.y;
            As[lc + 2][lr + rr] = a.z; As[lc + 3][lr + rr] = a.w;
            float4 b = *(const float4*)&B[(size_t)(n0 + lr + rr) * K + k0 + lc];
            Bs[lc + 0][lr + rr] = b.x; Bs[lc + 1][lr + rr] = b.y;
            Bs[lc + 2][lr + rr] = b.z; Bs[lc + 3][lr + rr] = b.w;
        }
        __syncthreads();

        #pragma unroll
        for (int k = 0; k < 16; k++) {
            float4 a0 = *(const float4*)&As[k][ty * 8];
            float4 a1 = *(const float4*)&As[k][ty * 8 + 4];
            float4 b0 = *(const float4*)&Bs[k][tx * 8];
            float4 b1 = *(const float4*)&Bs[k][tx * 8 + 4];
            float av[8] = {a0.x, a0.y, a0.z, a0.w, a1.x, a1.y, a1.z, a1.w};
            float bv[8] = {b0.x, b0.y, b0.z, b0.w, b1.x, b1.y, b1.z, b1.w};
            #pragma unroll
            for (int i = 0; i < 8; i++)
                #pragma unroll
                for (int j = 0; j < 8; j++)
                    acc[i][j] += av[i] * bv[j];
        }
        __syncthreads();
    }

    #pragma unroll
    for (int i = 0; i < 8; i++) {
        int m = m0 + ty * 8 + i;
        #pragma unroll
        for (int j = 0; j < 8; j++) {
            int n = n0 + tx * 8 + j;
            float v = acc[i][j] + bias[n];
            if (RESID) v += resid[(size_t)m * N + n];
            C[(size_t)m * N + n] = v;
        }
    }
}

// ------------------------------------------------------------- Attention
// One block = (b,h) pair x 64-query tile. Online softmax over 16 key tiles
// of 64. Layouts (dynamic smem, floats):
//   Qs[d][q]  stride 68, Ks[d][k] stride 68, Vs[k][d] stride 64, Ps[k][q] stride 68
#define QS_OFF 0
#define KS_OFF 4352
#define VS_OFF 8704
#define PS_OFF 12800
#define ATTN_SMEM_FLOATS 17152      /* 68608 bytes */

__global__ void __launch_bounds__(256) attn_kernel() {
    extern __shared__ __align__(16) float sm[];
    float* Qs = sm + QS_OFF;
    float* Ks = sm + KS_OFF;
    float* Vs = sm + VS_OFF;
    float* Ps = sm + PS_OFF;

    int tid = threadIdx.x;
    int bh = blockIdx.y;
    int b = bh >> 3, h = bh & 7;
    int q0 = blockIdx.x * 64;
    int tx = tid & 15, ty = tid >> 4;

    // Load Q tile transposed, pre-scaled by 1/sqrt(64)=0.125
    #pragma unroll
    for (int rep = 0; rep < 4; rep++) {
        int lin = tid + rep * 256;
        int r = lin >> 4;             // query row 0..63
        int c4 = (lin & 15) * 4;      // d
        int w = q0 + r;
        const float* src = &g_qkv[(size_t)(w * BSZ + b) * QKV_N + h * HEAD_DIM + c4];
        float4 q = *(const float4*)src;
        Qs[(c4 + 0) * 68 + r] = q.x * 0.125f;
        Qs[(c4 + 1) * 68 + r] = q.y * 0.125f;
        Qs[(c4 + 2) * 68 + r] = q.z * 0.125f;
        Qs[(c4 + 3) * 68 + r] = q.w * 0.125f;
    }

    float m_i[4], l_i[4], acc[4][4];
    #pragma unroll
    for (int i = 0; i < 4; i++) {
        m_i[i] = -1e30f; l_i[i] = 0.f;
        #pragma unroll
        for (int j = 0; j < 4; j++) acc[i][j] = 0.f;
    }

    for (int kt = 0; kt < W_LEN; kt += 64) {
        __syncthreads();   // prev Ps/Vs consumed; Q visible on first iter
        // Load K (transposed) and V tiles
        #pragma unroll
        for (int rep = 0; rep < 4; rep++) {
            int lin = tid + rep * 256;
            int r = lin >> 4;           // key row in tile
            int c4 = (lin & 15) * 4;
            int w = kt + r;
            const float* base = &g_qkv[(size_t)(w * BSZ + b) * QKV_N + h * HEAD_DIM];
            float4 kv = *(const float4*)(base + EMBED + c4);
            Ks[(c4 + 0) * 68 + r] = kv.x;
            Ks[(c4 + 1) * 68 + r] = kv.y;
            Ks[(c4 + 2) * 68 + r] = kv.z;
            Ks[(c4 + 3) * 68 + r] = kv.w;
            float4 vv = *(const float4*)(base + 2 * EMBED + c4);
            *(float4*)&Vs[r * 64 + c4] = vv;
        }
        __syncthreads();

        // S = Q K^T  (4x4 register tile per thread)
        float s[4][4];
        #pragma unroll
        for (int i = 0; i < 4; i++)
            #pragma unroll
            for (int j = 0; j < 4; j++) s[i][j] = 0.f;
        #pragma unroll 8
        for (int d = 0; d < 64; d++) {
            float4 q = *(const float4*)&Qs[d * 68 + ty * 4];
            float4 k = *(const float4*)&Ks[d * 68 + tx * 4];
            float qa[4] = {q.x, q.y, q.z, q.w};
            float ka[4] = {k.x, k.y, k.z, k.w};
            #pragma unroll
            for (int i = 0; i < 4; i++)
                #pragma unroll
                for (int j = 0; j < 4; j++)
                    s[i][j] += qa[i] * ka[j];
        }

        // Online softmax per query row (16 threads share a row, shfl width 16)
        #pragma unroll
        for (int i = 0; i < 4; i++) {
            float mx = fmaxf(fmaxf(s[i][0], s[i][1]), fmaxf(s[i][2], s[i][3]));
            #pragma unroll
            for (int o = 8; o; o >>= 1) mx = fmaxf(mx, __shfl_xor_sync(0xffffffffu, mx, o, 16));
            float mn = fmaxf(m_i[i], mx);
            float corr = __expf(m_i[i] - mn);
            float rs = 0.f;
            #pragma unroll
            for (int j = 0; j < 4; j++) {
                float p = __expf(s[i][j] - mn);
                Ps[(tx * 4 + j) * 68 + ty * 4 + i] = p;
                rs += p;
            }
            #pragma unroll
            for (int o = 8; o; o >>= 1) rs += __shfl_xor_sync(0xffffffffu, rs, o, 16);
            l_i[i] = l_i[i] * corr + rs;
            m_i[i] = mn;
            #pragma unroll
            for (int j = 0; j < 4; j++) acc[i][j] *= corr;
        }
        __syncthreads();

        // O += P V  (4x4 register tile)
        #pragma unroll 8
        for (int kc = 0; kc < 64; kc++) {
            float4 p = *(const float4*)&Ps[kc * 68 + ty * 4];
            float4 v = *(const float4*)&Vs[kc * 64 + tx * 4];
            float pa[4] = {p.x, p.y, p.z, p.w};
            float va[4] = {v.x, v.y, v.z, v.w};
            #pragma unroll
            for (int i = 0; i < 4; i++)
                #pragma unroll
                for (int j = 0; j < 4; j++)
                    acc[i][j] += pa[i] * va[j];
        }
    }

    // Epilogue: divide by l, write to g_attn
    #pragma unroll
    for (int i = 0; i < 4; i++) {
        float inv = 1.f / l_i[i];
        int w = q0 + ty * 4 + i;
        float4 o;
        o.x = acc[i][0] * inv; o.y = acc[i][1] * inv;
        o.z = acc[i][2] * inv; o.w = acc[i][3] * inv;
        *(float4*)&g_attn[(size_t)(w * BSZ + b) * EMBED + h * HEAD_DIM + tx * 4] = o;
    }
}

// ---------------------------------------------------------------- launcher
extern "C" void kernel_launch(void* const* d_in, const int* in_sizes, int n_in,
                              void* d_out, int out_size) {
    const float* feat  = (const float*)d_in[0];
    const float* in_w  = (const float*)d_in[1];
    const float* in_b  = (const float*)d_in[2];
    const float* out_w = (const float*)d_in[3];
    const float* out_b = (const float*)d_in[4];
    const float* ln_g  = (const float*)d_in[5];
    const float* ln_b  = (const float*)d_in[6];
    float* out = (float*)d_out;

    float *xnorm, *qkv, *attn;
    cudaGetSymbolAddress((void**)&xnorm, g_xnorm);
    cudaGetSymbolAddress((void**)&qkv,   g_qkv);
    cudaGetSymbolAddress((void**)&attn,  g_attn);

    static_assert(ATTN_SMEM_FLOATS * 4 == 68608, "smem layout");
    cudaFuncSetAttribute(attn_kernel, cudaFuncAttributeMaxDynamicSharedMemorySize,
                         ATTN_SMEM_FLOATS * 4);

    // 1. LayerNorm
    ln_kernel<<<M_ROWS, 256>>>(feat, ln_g, ln_b);

    // 2. QKV projection: [16384,512] x [1536,512]^T
    sgemm_tn<false><<<dim3(QKV_N / 128, M_ROWS / 128), 256>>>(
        xnorm, in_w, in_b, nullptr, qkv, QKV_N, EMBED);

    // 3. Attention: grid (query tiles, b*h)
    attn_kernel<<<dim3(W_LEN / 64, BSZ * NHEADS), 256, ATTN_SMEM_FLOATS * 4>>>();

    // 4. Out projection + bias + residual -> d_out
    sgemm_tn<true><<<dim3(EMBED / 128, M_ROWS / 128), 256>>>(
        attn, out_w, out_b, feat, out, EMBED, EMBED);
}

// round 4
// speedup vs baseline: 1.5030x; 1.5030x over previous
#include <cuda_runtime.h>
#include <cuda_bf16.h>
#include <cstdint>
#include <math.h>

#define W_LEN   1024
#define BSZ     16
#define EMBED   512
#define NHEADS  8
#define HEAD_DIM 64
#define M_ROWS  (W_LEN*BSZ)      /* 16384 */
#define QKV_N   (3*EMBED)        /* 1536  */
#define K2      1024             /* doubled K (hi|lo bf16 split) */

// ---------------- scratch (__device__ globals: no-alloc rule) ----------------
__device__ __align__(256) __nv_bfloat16 g_a16[M_ROWS * K2];     // LN output hi|lo
__device__ __align__(256) __nv_bfloat16 g_w16[QKV_N * K2];      // in_proj_w hi|lo
__device__ __align__(256) __nv_bfloat16 g_ow16[EMBED * K2];     // out_w hi|lo
__device__ __align__(256) __nv_bfloat16 g_attn16[M_ROWS * K2];  // attn out hi|lo
__device__ float g_qkv[M_ROWS * QKV_N];                         // fp32 qkv

// ---------------- helpers ----------------
__device__ __forceinline__ uint32_t smem_u32(const void* p) {
    uint32_t a;
    asm("{ .reg .u64 t; cvta.to.shared.u64 t, %1; cvt.u32.u64 %0, t; }" : "=r"(a) : "l"(p));
    return a;
}
__device__ __forceinline__ void split_bf16(float v, __nv_bfloat16& h, __nv_bfloat16& l) {
    h = __float2bfloat16(v);
    l = __float2bfloat16(v - __bfloat162float(h));
}
__device__ __forceinline__ void ldmatrix_x4(uint32_t* r, uint32_t addr) {
    asm volatile("ldmatrix.sync.aligned.m8n8.x4.shared.b16 {%0,%1,%2,%3}, [%4];"
                 : "=r"(r[0]), "=r"(r[1]), "=r"(r[2]), "=r"(r[3]) : "r"(addr));
}
__device__ __forceinline__ void mma16816(float* c, const uint32_t* a, uint32_t b0, uint32_t b1) {
    asm volatile("mma.sync.aligned.m16n8k16.row.col.f32.bf16.bf16.f32 "
                 "{%0,%1,%2,%3}, {%4,%5,%6,%7}, {%8,%9}, {%0,%1,%2,%3};"
                 : "+f"(c[0]), "+f"(c[1]), "+f"(c[2]), "+f"(c[3])
                 : "r"(a[0]), "r"(a[1]), "r"(a[2]), "r"(a[3]), "r"(b0), "r"(b1));
}
#define CP_ASYNC16(dst, src) \
    asm volatile("cp.async.cg.shared.global [%0], [%1], 16;" :: "r"(dst), "l"(src))
#define CP_COMMIT() asm volatile("cp.async.commit_group;" ::: "memory")
#define CP_WAIT(n)  asm volatile("cp.async.wait_group %0;" :: "n"(n) : "memory")

// ---------------------------------------------------------------- LayerNorm
// writes hi|lo bf16 A-matrix [M, 1024]
__global__ void __launch_bounds__(256) ln_kernel(const float* __restrict__ feat,
                                                 const float* __restrict__ gam,
                                                 const float* __restrict__ bet) {
    int row = blockIdx.x;
    int t = threadIdx.x;
    const float2 v = ((const float2*)(feat + (size_t)row * EMBED))[t];
    __shared__ float red[8];

    float s = v.x + v.y;
    #pragma unroll
    for (int o = 16; o; o >>= 1) s += __shfl_xor_sync(0xffffffffu, s, o);
    if ((t & 31) == 0) red[t >> 5] = s;
    __syncthreads();
    float tot = 0.f;
    #pragma unroll
    for (int i = 0; i < 8; i++) tot += red[i];
    float mu = tot * (1.f / EMBED);
    __syncthreads();

    float dx = v.x - mu, dy = v.y - mu;
    float s2 = dx * dx + dy * dy;
    #pragma unroll
    for (int o = 16; o; o >>= 1) s2 += __shfl_xor_sync(0xffffffffu, s2, o);
    if ((t & 31) == 0) red[t >> 5] = s2;
    __syncthreads();
    float var = 0.f;
    #pragma unroll
    for (int i = 0; i < 8; i++) var += red[i];
    float rstd = rsqrtf(var * (1.f / EMBED) + 1e-5f);

    float2 g2 = ((const float2*)gam)[t];
    float2 b2 = ((const float2*)bet)[t];
    float ox = dx * rstd * g2.x + b2.x;
    float oy = dy * rstd * g2.y + b2.y;

    __nv_bfloat16 hx, lx, hy, ly;
    split_bf16(ox, hx, lx);
    split_bf16(oy, hy, ly);
    size_t base = (size_t)row * K2;
    *(__nv_bfloat162*)&g_a16[base + 2 * t]       = __halves2bfloat162(hx, hy);
    *(__nv_bfloat162*)&g_a16[base + 512 + 2 * t] = __halves2bfloat162(lx, ly);
}

// ----------------------------------------------- weight fp32 -> hi|lo bf16
__global__ void wconv_kernel(const float* __restrict__ src, __nv_bfloat16* __restrict__ dst,
                             int total) {
    int idx = blockIdx.x * 256 + threadIdx.x;
    if (idx >= total) return;
    int r = idx >> 9, c = idx & 511;
    __nv_bfloat16 h, l;
    split_bf16(src[idx], h, l);
    dst[(size_t)r * K2 + c] = h;
    dst[(size_t)r * K2 + 512 + c] = l;
}

// --------------------------------------- mma.sync GEMM  C = A16 * B16^T
// A16 [M,1024] bf16 K-major, B16 [N,1024] bf16 K-major, C fp32 [M,N] + bias (+resid)
// Block 128x128, BK=64 (=128B rows, SW128 xor swizzle), 8 warps (2M x 4N),
// warp tile 64x32, m16n8k16 HMMA, double-buffered cp.async.
#define BM 128
#define BN 128
#define BK 64
#define NCHUNK (K2 / BK)          /* 16 */
#define ABUF 16384                /* 128 rows * 128B */
#define GEMM_SMEM (4 * ABUF)      /* A0 A1 B0 B1 = 64KB */

template <bool RESID>
__global__ void __launch_bounds__(256, 2) gemm_mma(const __nv_bfloat16* __restrict__ A,
                                                   const __nv_bfloat16* __restrict__ B,
                                                   const float* __restrict__ bias,
                                                   const float* __restrict__ resid,
                                                   float* __restrict__ C, int N) {
    extern __shared__ __align__(1024) char smem[];
    uint32_t sb = smem_u32(smem);
    int tid = threadIdx.x;
    int lid = tid & 31, wid = tid >> 5;
    int wm = wid & 1, wn = wid >> 1;          // warp grid 2(M) x 4(N)
    int m0 = blockIdx.y * BM, n0 = blockIdx.x * BN;

    const __nv_bfloat16* Ablk = A + (size_t)m0 * K2;
    const __nv_bfloat16* Bblk = B + (size_t)n0 * K2;

    float acc[4][4][4];
    #pragma unroll
    for (int i = 0; i < 4; i++)
        #pragma unroll
        for (int j = 0; j < 4; j++)
            #pragma unroll
            for (int k = 0; k < 4; k++) acc[i][j][k] = 0.f;

    auto load_chunk = [&](int c, int s) {
        int koff = c * BK;
        uint32_t abase = sb + s * ABUF;
        uint32_t bbase = sb + 2 * ABUF + s * ABUF;
        #pragma unroll
        for (int i = 0; i < 4; i++) {
            int idx = tid + i * 256;
            int row = idx >> 3, g = idx & 7;
            uint32_t dst = abase + row * 128 + ((g ^ (row & 7)) << 4);
            CP_ASYNC16(dst, Ablk + (size_t)row * K2 + koff + g * 8);
        }
        #pragma unroll
        for (int i = 0; i < 4; i++) {
            int idx = tid + i * 256;
            int row = idx >> 3, g = idx & 7;
            uint32_t dst = bbase + row * 128 + ((g ^ (row & 7)) << 4);
            CP_ASYNC16(dst, Bblk + (size_t)row * K2 + koff + g * 8);
        }
        CP_COMMIT();
    };

    load_chunk(0, 0);

    for (int c = 0; c < NCHUNK; c++) {
        int s = c & 1;
        if (c + 1 < NCHUNK) { load_chunk(c + 1, s ^ 1); CP_WAIT(1); }
        else                { CP_WAIT(0); }
        __syncthreads();

        uint32_t abase = sb + s * ABUF;
        uint32_t bbase = sb + 2 * ABUF + s * ABUF;
        #pragma unroll
        for (int ks = 0; ks < 4; ks++) {          // 4 k16-steps per BK=64
            uint32_t afr[4][4];
            #pragma unroll
            for (int mi = 0; mi < 4; mi++) {
                int row = wm * 64 + mi * 16 + (lid & 15);
                int chunk = ks * 2 + (lid >> 4);
                ldmatrix_x4(afr[mi], abase + row * 128 + ((chunk ^ (row & 7)) << 4));
            }
            uint32_t bfr[2][4];
            #pragma unroll
            for (int nf = 0; nf < 2; nf++) {
                int row = wn * 32 + nf * 16 + (lid & 7) + ((lid & 16) >> 1);
                int chunk = ks * 2 + ((lid & 8) >> 3);
                ldmatrix_x4(bfr[nf], bbase + row * 128 + ((chunk ^ (row & 7)) << 4));
            }
            #pragma unroll
            for (int mi = 0; mi < 4; mi++)
                #pragma unroll
                for (int nj = 0; nj < 4; nj++) {
                    const uint32_t* b = bfr[nj >> 1];
                    int p = (nj & 1) * 2;
                    mma16816(acc[mi][nj], afr[mi], b[p], b[p + 1]);
                }
        }
        __syncthreads();
    }

    // epilogue: C frag thread layout: rows (lid>>2), (lid>>2)+8; cols 2*(lid&3)
    #pragma unroll
    for (int mi = 0; mi < 4; mi++) {
        int mA = m0 + wm * 64 + mi * 16 + (lid >> 2);
        #pragma unroll
        for (int nj = 0; nj < 4; nj++) {
            int n = n0 + wn * 32 + nj * 8 + 2 * (lid & 3);
            float bx = bias[n], by = bias[n + 1];
            float2 v0 = make_float2(acc[mi][nj][0] + bx, acc[mi][nj][1] + by);
            float2 v1 = make_float2(acc[mi][nj][2] + bx, acc[mi][nj][3] + by);
            if (RESID) {
                float2 r0 = *(const float2*)&resid[(size_t)mA * N + n];
                float2 r1 = *(const float2*)&resid[(size_t)(mA + 8) * N + n];
                v0.x += r0.x; v0.y += r0.y; v1.x += r1.x; v1.y += r1.y;
            }
            *(float2*)&C[(size_t)mA * N + n] = v0;
            *(float2*)&C[(size_t)(mA + 8) * N + n] = v1;
        }
    }
}

// ------------------------------------------------------------- Attention (SIMT)
#define QS_OFF 0
#define KS_OFF 4352
#define VS_OFF 8704
#define PS_OFF 12800
#define ATTN_SMEM_FLOATS 17152      /* 68608 bytes */

__global__ void __launch_bounds__(256) attn_kernel() {
    extern __shared__ __align__(16) float sm[];
    float* Qs = sm + QS_OFF;
    float* Ks = sm + KS_OFF;
    float* Vs = sm + VS_OFF;
    float* Ps = sm + PS_OFF;

    int tid = threadIdx.x;
    int bh = blockIdx.y;
    int b = bh >> 3, h = bh & 7;
    int q0 = blockIdx.x * 64;
    int tx = tid & 15, ty = tid >> 4;

    #pragma unroll
    for (int rep = 0; rep < 4; rep++) {
        int lin = tid + rep * 256;
        int r = lin >> 4;
        int c4 = (lin & 15) * 4;
        int w = q0 + r;
        const float* src = &g_qkv[(size_t)(w * BSZ + b) * QKV_N + h * HEAD_DIM + c4];
        float4 q = *(const float4*)src;
        Qs[(c4 + 0) * 68 + r] = q.x * 0.125f;
        Qs[(c4 + 1) * 68 + r] = q.y * 0.125f;
        Qs[(c4 + 2) * 68 + r] = q.z * 0.125f;
        Qs[(c4 + 3) * 68 + r] = q.w * 0.125f;
    }

    float m_i[4], l_i[4], acc[4][4];
    #pragma unroll
    for (int i = 0; i < 4; i++) {
        m_i[i] = -1e30f; l_i[i] = 0.f;
        #pragma unroll
        for (int j = 0; j < 4; j++) acc[i][j] = 0.f;
    }

    for (int kt = 0; kt < W_LEN; kt += 64) {
        __syncthreads();
        #pragma unroll
        for (int rep = 0; rep < 4; rep++) {
            int lin = tid + rep * 256;
            int r = lin >> 4;
            int c4 = (lin & 15) * 4;
            int w = kt + r;
            const float* base = &g_qkv[(size_t)(w * BSZ + b) * QKV_N + h * HEAD_DIM];
            float4 kv = *(const float4*)(base + EMBED + c4);
            Ks[(c4 + 0) * 68 + r] = kv.x;
            Ks[(c4 + 1) * 68 + r] = kv.y;
            Ks[(c4 + 2) * 68 + r] = kv.z;
            Ks[(c4 + 3) * 68 + r] = kv.w;
            float4 vv = *(const float4*)(base + 2 * EMBED + c4);
            *(float4*)&Vs[r * 64 + c4] = vv;
        }
        __syncthreads();

        float s[4][4];
        #pragma unroll
        for (int i = 0; i < 4; i++)
            #pragma unroll
            for (int j = 0; j < 4; j++) s[i][j] = 0.f;
        #pragma unroll 8
        for (int d = 0; d < 64; d++) {
            float4 q = *(const float4*)&Qs[d * 68 + ty * 4];
            float4 k = *(const float4*)&Ks[d * 68 + tx * 4];
            float qa[4] = {q.x, q.y, q.z, q.w};
            float ka[4] = {k.x, k.y, k.z, k.w};
            #pragma unroll
            for (int i = 0; i < 4; i++)
                #pragma unroll
                for (int j = 0; j < 4; j++)
                    s[i][j] += qa[i] * ka[j];
        }

        #pragma unroll
        for (int i = 0; i < 4; i++) {
            float mx = fmaxf(fmaxf(s[i][0], s[i][1]), fmaxf(s[i][2], s[i][3]));
            #pragma unroll
            for (int o = 8; o; o >>= 1) mx = fmaxf(mx, __shfl_xor_sync(0xffffffffu, mx, o, 16));
            float mn = fmaxf(m_i[i], mx);
            float corr = __expf(m_i[i] - mn);
            float rs = 0.f;
            #pragma unroll
            for (int j = 0; j < 4; j++) {
                float p = __expf(s[i][j] - mn);
                Ps[(tx * 4 + j) * 68 + ty * 4 + i] = p;
                rs += p;
            }
            #pragma unroll
            for (int o = 8; o; o >>= 1) rs += __shfl_xor_sync(0xffffffffu, rs, o, 16);
            l_i[i] = l_i[i] * corr + rs;
            m_i[i] = mn;
            #pragma unroll
            for (int j = 0; j < 4; j++) acc[i][j] *= corr;
        }
        __syncthreads();

        #pragma unroll 8
        for (int kc = 0; kc < 64; kc++) {
            float4 p = *(const float4*)&Ps[kc * 68 + ty * 4];
            float4 v = *(const float4*)&Vs[kc * 64 + tx * 4];
            float pa[4] = {p.x, p.y, p.z, p.w};
            float va[4] = {v.x, v.y, v.z, v.w};
            #pragma unroll
            for (int i = 0; i < 4; i++)
                #pragma unroll
                for (int j = 0; j < 4; j++)
                    acc[i][j] += pa[i] * va[j];
        }
    }

    // epilogue: normalize, write hi|lo bf16 for out-proj GEMM
    #pragma unroll
    for (int i = 0; i < 4; i++) {
        float inv = 1.f / l_i[i];
        int w = q0 + ty * 4 + i;
        size_t base = (size_t)(w * BSZ + b) * K2 + h * HEAD_DIM + tx * 4;
        float o0 = acc[i][0] * inv, o1 = acc[i][1] * inv;
        float o2 = acc[i][2] * inv, o3 = acc[i][3] * inv;
        __nv_bfloat16 h0, l0, h1, l1, h2, l2, h3, l3;
        split_bf16(o0, h0, l0); split_bf16(o1, h1, l1);
        split_bf16(o2, h2, l2); split_bf16(o3, h3, l3);
        *(__nv_bfloat162*)&g_attn16[base]           = __halves2bfloat162(h0, h1);
        *(__nv_bfloat162*)&g_attn16[base + 2]       = __halves2bfloat162(h2, h3);
        *(__nv_bfloat162*)&g_attn16[base + 512]     = __halves2bfloat162(l0, l1);
        *(__nv_bfloat162*)&g_attn16[base + 512 + 2] = __halves2bfloat162(l2, l3);
    }
}

// ---------------------------------------------------------------- launcher
extern "C" void kernel_launch(void* const* d_in, const int* in_sizes, int n_in,
                              void* d_out, int out_size) {
    const float* feat  = (const float*)d_in[0];
    const float* in_w  = (const float*)d_in[1];
    const float* in_b  = (const float*)d_in[2];
    const float* out_w = (const float*)d_in[3];
    const float* out_b = (const float*)d_in[4];
    const float* ln_g  = (const float*)d_in[5];
    const float* ln_b  = (const float*)d_in[6];
    float* out = (float*)d_out;

    __nv_bfloat16 *a16, *w16, *ow16, *attn16;
    float* qkv;
    cudaGetSymbolAddress((void**)&a16,    g_a16);
    cudaGetSymbolAddress((void**)&w16,    g_w16);
    cudaGetSymbolAddress((void**)&ow16,   g_ow16);
    cudaGetSymbolAddress((void**)&attn16, g_attn16);
    cudaGetSymbolAddress((void**)&qkv,    g_qkv);

    cudaFuncSetAttribute(gemm_mma<false>, cudaFuncAttributeMaxDynamicSharedMemorySize, GEMM_SMEM);
    cudaFuncSetAttribute(gemm_mma<true>,  cudaFuncAttributeMaxDynamicSharedMemorySize, GEMM_SMEM);
    cudaFuncSetAttribute(attn_kernel, cudaFuncAttributeMaxDynamicSharedMemorySize,
                         ATTN_SMEM_FLOATS * 4);

    // 1. LayerNorm -> hi|lo bf16 A
    ln_kernel<<<M_ROWS, 256>>>(feat, ln_g, ln_b);

    // 2. weight conversions
    wconv_kernel<<<(QKV_N * EMBED + 255) / 256, 256>>>(in_w, w16, QKV_N * EMBED);
    wconv_kernel<<<(EMBED * EMBED + 255) / 256, 256>>>(out_w, ow16, EMBED * EMBED);

    // 3. QKV projection (HMMA): [16384,1024] x [1536,1024]^T -> fp32
    gemm_mma<false><<<dim3(QKV_N / BN, M_ROWS / BM), 256, GEMM_SMEM>>>(
        a16, w16, in_b, nullptr, qkv, QKV_N);

    // 4. Attention (SIMT fp32) -> hi|lo bf16
    attn_kernel<<<dim3(W_LEN / 64, BSZ * NHEADS), 256, ATTN_SMEM_FLOATS * 4>>>();

    // 5. Out projection (HMMA) + bias + residual -> d_out
    gemm_mma<true><<<dim3(EMBED / BN, M_ROWS / BM), 256, GEMM_SMEM>>>(
        attn16, ow16, out_b, feat, out, EMBED);
}

// round 5
// speedup vs baseline: 3.2388x; 2.1549x over previous
#include <cuda_runtime.h>
#include <cuda_bf16.h>
#include <cstdint>
#include <math.h>

#define W_LEN   1024
#define BSZ     16
#define EMBED   512
#define NHEADS  8
#define HEAD_DIM 64
#define M_ROWS  (W_LEN*BSZ)      /* 16384 */
#define QKV_N   (3*EMBED)        /* 1536  */
#define KTOT    1536             /* tripled K: [Ah|Al|Ah] x [Bh|Bh|Bl] */

// ---------------- scratch (__device__ globals: no-alloc rule) ----------------
__device__ __align__(256) __nv_bfloat16 g_a16[M_ROWS * KTOT];    // LN out [Ah|Al|Ah]
__device__ __align__(256) __nv_bfloat16 g_w16[QKV_N * KTOT];     // in_w  [Wh|Wh|Wl]
__device__ __align__(256) __nv_bfloat16 g_ow16[EMBED * KTOT];    // out_w [Wh|Wh|Wl]
__device__ __align__(256) __nv_bfloat16 g_attn16[M_ROWS * KTOT]; // attn out [Ah|Al|Ah]
// attention operands, layout [bh][w][d] (bh = b*8+h)
#define BHWD (BSZ*NHEADS*W_LEN*HEAD_DIM)
__device__ __align__(256) __nv_bfloat16 g_qh[BHWD], g_ql[BHWD];
__device__ __align__(256) __nv_bfloat16 g_kh[BHWD], g_kl[BHWD];
__device__ __align__(256) __nv_bfloat16 g_vh[BHWD], g_vl[BHWD];

// ---------------- helpers ----------------
__device__ __forceinline__ uint32_t smem_u32(const void* p) {
    uint32_t a;
    asm("{ .reg .u64 t; cvta.to.shared.u64 t, %1; cvt.u32.u64 %0, t; }" : "=r"(a) : "l"(p));
    return a;
}
__device__ __forceinline__ void split_bf16(float v, __nv_bfloat16& h, __nv_bfloat16& l) {
    h = __float2bfloat16(v);
    l = __float2bfloat16(v - __bfloat162float(h));
}
// split two floats -> packed hi pair + lo pair
__device__ __forceinline__ void split2(float x, float y, uint32_t& hi, uint32_t& lo) {
    __nv_bfloat16 hx, lx, hy, ly;
    split_bf16(x, hx, lx);
    split_bf16(y, hy, ly);
    __nv_bfloat162 th = __halves2bfloat162(hx, hy);
    __nv_bfloat162 tl = __halves2bfloat162(lx, ly);
    hi = *reinterpret_cast<uint32_t*>(&th);
    lo = *reinterpret_cast<uint32_t*>(&tl);
}
__device__ __forceinline__ void ldmatrix_x4(uint32_t* r, uint32_t addr) {
    asm volatile("ldmatrix.sync.aligned.m8n8.x4.shared.b16 {%0,%1,%2,%3}, [%4];"
                 : "=r"(r[0]), "=r"(r[1]), "=r"(r[2]), "=r"(r[3]) : "r"(addr));
}
__device__ __forceinline__ void ldmatrix_x4_trans(uint32_t* r, uint32_t addr) {
    asm volatile("ldmatrix.sync.aligned.m8n8.x4.trans.shared.b16 {%0,%1,%2,%3}, [%4];"
                 : "=r"(r[0]), "=r"(r[1]), "=r"(r[2]), "=r"(r[3]) : "r"(addr));
}
__device__ __forceinline__ void mma16816(float* c, const uint32_t* a, uint32_t b0, uint32_t b1) {
    asm volatile("mma.sync.aligned.m16n8k16.row.col.f32.bf16.bf16.f32 "
                 "{%0,%1,%2,%3}, {%4,%5,%6,%7}, {%8,%9}, {%0,%1,%2,%3};"
                 : "+f"(c[0]), "+f"(c[1]), "+f"(c[2]), "+f"(c[3])
                 : "r"(a[0]), "r"(a[1]), "r"(a[2]), "r"(a[3]), "r"(b0), "r"(b1));
}
#define CP_ASYNC16(dst, src) \
    asm volatile("cp.async.cg.shared.global [%0], [%1], 16;" :: "r"(dst), "l"(src))
#define CP_COMMIT() asm volatile("cp.async.commit_group;" ::: "memory")
#define CP_WAIT(n)  asm volatile("cp.async.wait_group %0;" :: "n"(n) : "memory")

// ---------------------------------------------------------------- LayerNorm
// writes [Ah | Al | Ah] bf16 A-matrix [M, 1536]
__global__ void __launch_bounds__(256) ln_kernel(const float* __restrict__ feat,
                                                 const float* __restrict__ gam,
                                                 const float* __restrict__ bet) {
    int row = blockIdx.x;
    int t = threadIdx.x;
    const float2 v = ((const float2*)(feat + (size_t)row * EMBED))[t];
    __shared__ float red[8];

    float s = v.x + v.y;
    #pragma unroll
    for (int o = 16; o; o >>= 1) s += __shfl_xor_sync(0xffffffffu, s, o);
    if ((t & 31) == 0) red[t >> 5] = s;
    __syncthreads();
    float tot = 0.f;
    #pragma unroll
    for (int i = 0; i < 8; i++) tot += red[i];
    float mu = tot * (1.f / EMBED);
    __syncthreads();

    float dx = v.x - mu, dy = v.y - mu;
    float s2 = dx * dx + dy * dy;
    #pragma unroll
    for (int o = 16; o; o >>= 1) s2 += __shfl_xor_sync(0xffffffffu, s2, o);
    if ((t & 31) == 0) red[t >> 5] = s2;
    __syncthreads();
    float var = 0.f;
    #pragma unroll
    for (int i = 0; i < 8; i++) var += red[i];
    float rstd = rsqrtf(var * (1.f / EMBED) + 1e-5f);

    float2 g2 = ((const float2*)gam)[t];
    float2 b2 = ((const float2*)bet)[t];
    float ox = dx * rstd * g2.x + b2.x;
    float oy = dy * rstd * g2.y + b2.y;

    uint32_t hi, lo;
    split2(ox, oy, hi, lo);
    size_t base = (size_t)row * KTOT;
    *(uint32_t*)&g_a16[base + 2 * t]        = hi;
    *(uint32_t*)&g_a16[base + 512 + 2 * t]  = lo;
    *(uint32_t*)&g_a16[base + 1024 + 2 * t] = hi;
}

// ------------------------------------- weight fp32 -> [Wh|Wh|Wl] bf16
__global__ void wconv_kernel(const float* __restrict__ src, __nv_bfloat16* __restrict__ dst,
                             int total) {
    int idx = blockIdx.x * 256 + threadIdx.x;
    if (idx >= total) return;
    int r = idx >> 9, c = idx & 511;
    __nv_bfloat16 h, l;
    split_bf16(src[idx], h, l);
    size_t base = (size_t)r * KTOT;
    dst[base + c] = h;
    dst[base + 512 + c] = h;
    dst[base + 1024 + c] = l;
}

// --------------------------------------- mma.sync GEMM  C = A16 * B16^T
// A16 [M,1536] bf16, B16 [N,1536] bf16. MODE 0: C=fp32+bias. MODE 1: +resid.
// MODE 2: QKV split-write to g_qh/ql/kh/kl/vh/vl (C unused).
#define BM 128
#define BN 128
#define BK 64
#define NCHUNK (KTOT / BK)        /* 24 */
#define ABUF 16384
#define GEMM_SMEM (4 * ABUF)

template <int MODE>
__global__ void __launch_bounds__(256, 2) gemm_mma(const __nv_bfloat16* __restrict__ A,
                                                   const __nv_bfloat16* __restrict__ B,
                                                   const float* __restrict__ bias,
                                                   const float* __restrict__ resid,
                                                   float* __restrict__ C, int N) {
    extern __shared__ __align__(1024) char smem[];
    uint32_t sb = smem_u32(smem);
    int tid = threadIdx.x;
    int lid = tid & 31, wid = tid >> 5;
    int wm = wid & 1, wn = wid >> 1;
    int m0 = blockIdx.y * BM, n0 = blockIdx.x * BN;

    const __nv_bfloat16* Ablk = A + (size_t)m0 * KTOT;
    const __nv_bfloat16* Bblk = B + (size_t)n0 * KTOT;

    float acc[4][4][4];
    #pragma unroll
    for (int i = 0; i < 4; i++)
        #pragma unroll
        for (int j = 0; j < 4; j++)
            #pragma unroll
            for (int k = 0; k < 4; k++) acc[i][j][k] = 0.f;

    auto load_chunk = [&](int c, int s) {
        int koff = c * BK;
        uint32_t abase = sb + s * ABUF;
        uint32_t bbase = sb + 2 * ABUF + s * ABUF;
        #pragma unroll
        for (int i = 0; i < 4; i++) {
            int idx = tid + i * 256;
            int row = idx >> 3, g = idx & 7;
            uint32_t dst = abase + row * 128 + ((g ^ (row & 7)) << 4);
            CP_ASYNC16(dst, Ablk + (size_t)row * KTOT + koff + g * 8);
        }
        #pragma unroll
        for (int i = 0; i < 4; i++) {
            int idx = tid + i * 256;
            int row = idx >> 3, g = idx & 7;
            uint32_t dst = bbase + row * 128 + ((g ^ (row & 7)) << 4);
            CP_ASYNC16(dst, Bblk + (size_t)row * KTOT + koff + g * 8);
        }
        CP_COMMIT();
    };

    load_chunk(0, 0);

    for (int c = 0; c < NCHUNK; c++) {
        int s = c & 1;
        if (c + 1 < NCHUNK) { load_chunk(c + 1, s ^ 1); CP_WAIT(1); }
        else                { CP_WAIT(0); }
        __syncthreads();

        uint32_t abase = sb + s * ABUF;
        uint32_t bbase = sb + 2 * ABUF + s * ABUF;
        #pragma unroll
        for (int ks = 0; ks < 4; ks++) {
            uint32_t afr[4][4];
            #pragma unroll
            for (int mi = 0; mi < 4; mi++) {
                int row = wm * 64 + mi * 16 + (lid & 15);
                int chunk = ks * 2 + (lid >> 4);
                ldmatrix_x4(afr[mi], abase + row * 128 + ((chunk ^ (row & 7)) << 4));
            }
            uint32_t bfr[2][4];
            #pragma unroll
            for (int nf = 0; nf < 2; nf++) {
                int row = wn * 32 + nf * 16 + (lid & 7) + ((lid & 16) >> 1);
                int chunk = ks * 2 + ((lid & 8) >> 3);
                ldmatrix_x4(bfr[nf], bbase + row * 128 + ((chunk ^ (row & 7)) << 4));
            }
            #pragma unroll
            for (int mi = 0; mi < 4; mi++)
                #pragma unroll
                for (int nj = 0; nj < 4; nj++) {
                    const uint32_t* b = bfr[nj >> 1];
                    int p = (nj & 1) * 2;
                    mma16816(acc[mi][nj], afr[mi], b[p], b[p + 1]);
                }
        }
        __syncthreads();
    }

    if (MODE < 2) {
        #pragma unroll
        for (int mi = 0; mi < 4; mi++) {
            int mA = m0 + wm * 64 + mi * 16 + (lid >> 2);
            #pragma unroll
            for (int nj = 0; nj < 4; nj++) {
                int n = n0 + wn * 32 + nj * 8 + 2 * (lid & 3);
                float bx = bias[n], by = bias[n + 1];
                float2 v0 = make_float2(acc[mi][nj][0] + bx, acc[mi][nj][1] + by);
                float2 v1 = make_float2(acc[mi][nj][2] + bx, acc[mi][nj][3] + by);
                if (MODE == 1) {
                    float2 r0 = *(const float2*)&resid[(size_t)mA * N + n];
                    float2 r1 = *(const float2*)&resid[(size_t)(mA + 8) * N + n];
                    v0.x += r0.x; v0.y += r0.y; v1.x += r1.x; v1.y += r1.y;
                }
                *(float2*)&C[(size_t)mA * N + n] = v0;
                *(float2*)&C[(size_t)(mA + 8) * N + n] = v1;
            }
        }
    } else {
        // QKV epilogue: split-write into attention layout [bh][w][d]
        #pragma unroll
        for (int mi = 0; mi < 4; mi++) {
            int mbase = m0 + wm * 64 + mi * 16 + (lid >> 2);
            #pragma unroll
            for (int nj = 0; nj < 4; nj++) {
                int n = n0 + wn * 32 + nj * 8 + 2 * (lid & 3);
                int region = n >> 9;
                int hh = (n & 511) >> 6;
                int d = n & 63;
                float bx = bias[n], by = bias[n + 1];
                __nv_bfloat16* dh = (region == 0) ? g_qh : (region == 1) ? g_kh : g_vh;
                __nv_bfloat16* dl = (region == 0) ? g_ql : (region == 1) ? g_kl : g_vl;
                #pragma unroll
                for (int rr = 0; rr < 2; rr++) {
                    int m = mbase + rr * 8;
                    int w = m >> 4, b = m & 15;
                    float vx = acc[mi][nj][rr * 2 + 0] + bx;
                    float vy = acc[mi][nj][rr * 2 + 1] + by;
                    if (region == 0) { vx *= 0.125f; vy *= 0.125f; }
                    uint32_t hi, lo;
                    split2(vx, vy, hi, lo);
                    size_t off = ((size_t)(b * 8 + hh) * W_LEN + w) * HEAD_DIM + d;
                    *(uint32_t*)&dh[off] = hi;
                    *(uint32_t*)&dl[off] = lo;
                }
            }
        }
    }
}

// ------------------------------------------------------------- Attention (HMMA)
// 128 threads (4 warps), 64-query tile, 64-key blocks, double-buffered K/V.
// 3-term hi/lo split on both QK^T and PV.
#define AT_QH 0
#define AT_QL 8192
#define AT_K0 16384            /* Kh[s] at AT_K0 + s*16384, Kl at +8192 */
#define AT_V0 49152
#define ATTN_SMEM 81920

__global__ void __launch_bounds__(128) attn_mma(__nv_bfloat16* __restrict__ attn16) {
    extern __shared__ __align__(1024) char smem[];
    uint32_t sb = smem_u32(smem);
    int tid = threadIdx.x;
    int lid = tid & 31, wid = tid >> 5;
    int bh = blockIdx.y;
    int q0 = blockIdx.x * 64;
    size_t gbase = (size_t)bh * (W_LEN * HEAD_DIM);

    auto ldtile = [&](uint32_t dstbase, const __nv_bfloat16* src, int row0) {
        #pragma unroll
        for (int i = 0; i < 4; i++) {
            int idx = tid + i * 128;
            int row = idx >> 3, g = idx & 7;
            uint32_t dst = dstbase + row * 128 + ((g ^ (row & 7)) << 4);
            CP_ASYNC16(dst, src + gbase + (size_t)(row0 + row) * HEAD_DIM + g * 8);
        }
    };

    ldtile(sb + AT_QH, g_qh, q0);
    ldtile(sb + AT_QL, g_ql, q0);
    ldtile(sb + AT_K0, g_kh, 0);
    ldtile(sb + AT_K0 + 8192, g_kl, 0);
    ldtile(sb + AT_V0, g_vh, 0);
    ldtile(sb + AT_V0 + 8192, g_vl, 0);
    CP_COMMIT();

    float o[8][4];
    #pragma unroll
    for (int i = 0; i < 8; i++)
        #pragma unroll
        for (int j = 0; j < 4; j++) o[i][j] = 0.f;
    float mrow[2] = {-1e30f, -1e30f};
    float lrow[2] = {0.f, 0.f};

    for (int kt = 0; kt < 16; kt++) {
        int s = kt & 1;
        if (kt < 15) {
            int r0 = (kt + 1) * 64;
            ldtile(sb + AT_K0 + (s ^ 1) * 16384,        g_kh, r0);
            ldtile(sb + AT_K0 + (s ^ 1) * 16384 + 8192, g_kl, r0);
            ldtile(sb + AT_V0 + (s ^ 1) * 16384,        g_vh, r0);
            ldtile(sb + AT_V0 + (s ^ 1) * 16384 + 8192, g_vl, r0);
            CP_COMMIT();
            CP_WAIT(1);
        } else {
            CP_WAIT(0);
        }
        __syncthreads();

        uint32_t kbase = sb + AT_K0 + s * 16384;
        uint32_t vbase = sb + AT_V0 + s * 16384;

        // ---- S = Q K^T (3-term) ----
        float sc[8][4];
        #pragma unroll
        for (int i = 0; i < 8; i++)
            #pragma unroll
            for (int j = 0; j < 4; j++) sc[i][j] = 0.f;

        #pragma unroll
        for (int ks = 0; ks < 4; ks++) {
            uint32_t ah[4], al[4];
            {
                int row = wid * 16 + (lid & 15);
                int ch = ks * 2 + (lid >> 4);
                uint32_t off = row * 128 + ((ch ^ (row & 7)) << 4);
                ldmatrix_x4(ah, sb + AT_QH + off);
                ldmatrix_x4(al, sb + AT_QL + off);
            }
            #pragma unroll
            for (int nf = 0; nf < 4; nf++) {
                uint32_t bhf[4], blf[4];
                int row = nf * 16 + (lid & 7) + ((lid & 16) >> 1);
                int ch = ks * 2 + ((lid & 8) >> 3);
                uint32_t off = row * 128 + ((ch ^ (row & 7)) << 4);
                ldmatrix_x4(bhf, kbase + off);
                ldmatrix_x4(blf, kbase + 8192 + off);
                #pragma unroll
                for (int t = 0; t < 2; t++) {
                    float* c = sc[nf * 2 + t];
                    mma16816(c, ah, bhf[t * 2], bhf[t * 2 + 1]);
                    mma16816(c, al, bhf[t * 2], bhf[t * 2 + 1]);
                    mma16816(c, ah, blf[t * 2], blf[t * 2 + 1]);
                }
            }
        }

        // ---- online softmax ----
        float mx0 = -1e30f, mx1 = -1e30f;
        #pragma unroll
        for (int j = 0; j < 8; j++) {
            mx0 = fmaxf(mx0, fmaxf(sc[j][0], sc[j][1]));
            mx1 = fmaxf(mx1, fmaxf(sc[j][2], sc[j][3]));
        }
        #pragma unroll
        for (int ofs = 1; ofs <= 2; ofs <<= 1) {
            mx0 = fmaxf(mx0, __shfl_xor_sync(0xffffffffu, mx0, ofs));
            mx1 = fmaxf(mx1, __shfl_xor_sync(0xffffffffu, mx1, ofs));
        }
        float mn0 = fmaxf(mrow[0], mx0), mn1 = fmaxf(mrow[1], mx1);
        float corr0 = __expf(mrow[0] - mn0), corr1 = __expf(mrow[1] - mn1);
        mrow[0] = mn0; mrow[1] = mn1;

        float sum0 = 0.f, sum1 = 0.f;
        #pragma unroll
        for (int j = 0; j < 8; j++) {
            sc[j][0] = __expf(sc[j][0] - mn0);
            sc[j][1] = __expf(sc[j][1] - mn0);
            sc[j][2] = __expf(sc[j][2] - mn1);
            sc[j][3] = __expf(sc[j][3] - mn1);
            sum0 += sc[j][0] + sc[j][1];
            sum1 += sc[j][2] + sc[j][3];
        }
        #pragma unroll
        for (int ofs = 1; ofs <= 2; ofs <<= 1) {
            sum0 += __shfl_xor_sync(0xffffffffu, sum0, ofs);
            sum1 += __shfl_xor_sync(0xffffffffu, sum1, ofs);
        }
        lrow[0] = lrow[0] * corr0 + sum0;
        lrow[1] = lrow[1] * corr1 + sum1;
        #pragma unroll
        for (int nd = 0; nd < 8; nd++) {
            o[nd][0] *= corr0; o[nd][1] *= corr0;
            o[nd][2] *= corr1; o[nd][3] *= corr1;
        }

        // ---- P frags (hi + lo) ----
        uint32_t ph[4][4], pl[4][4];
        #pragma unroll
        for (int kc = 0; kc < 4; kc++) {
            int j0 = kc * 2, j1 = kc * 2 + 1;
            split2(sc[j0][0], sc[j0][1], ph[kc][0], pl[kc][0]);
            split2(sc[j0][2], sc[j0][3], ph[kc][1], pl[kc][1]);
            split2(sc[j1][0], sc[j1][1], ph[kc][2], pl[kc][2]);
            split2(sc[j1][2], sc[j1][3], ph[kc][3], pl[kc][3]);
        }

        // ---- O += P V (3-term) ----
        #pragma unroll
        for (int kc = 0; kc < 4; kc++) {
            #pragma unroll
            for (int np = 0; np < 4; np++) {
                uint32_t vhf[4], vlf[4];
                int row = kc * 16 + (lid & 7) + ((lid >> 3) & 1) * 8;
                int c16 = np * 2 + ((lid >> 4) & 1);
                uint32_t off = row * 128 + ((c16 ^ (row & 7)) << 4);
                ldmatrix_x4_trans(vhf, vbase + off);
                ldmatrix_x4_trans(vlf, vbase + 8192 + off);
                #pragma unroll
                for (int t = 0; t < 2; t++) {
                    float* c = o[np * 2 + t];
                    mma16816(c, ph[kc], vhf[t * 2], vhf[t * 2 + 1]);
                    mma16816(c, pl[kc], vhf[t * 2], vhf[t * 2 + 1]);
                    mma16816(c, ph[kc], vlf[t * 2], vlf[t * 2 + 1]);
                }
            }
        }
        __syncthreads();
    }

    // ---- epilogue: normalize, split, write [Ah|Al|Ah] ----
    float inv0 = 1.f / lrow[0], inv1 = 1.f / lrow[1];
    int b = bh >> 3, h = bh & 7;
    int r0 = lid >> 2, c0 = (lid & 3) * 2;
    #pragma unroll
    for (int nd = 0; nd < 8; nd++) {
        int d = nd * 8 + c0;
        int col = h * HEAD_DIM + d;
        #pragma unroll
        for (int rr = 0; rr < 2; rr++) {
            int w = q0 + wid * 16 + r0 + rr * 8;
            int m = w * BSZ + b;
            float inv = rr ? inv1 : inv0;
            float vx = o[nd][rr * 2 + 0] * inv;
            float vy = o[nd][rr * 2 + 1] * inv;
            uint32_t hi, lo;
            split2(vx, vy, hi, lo);
            size_t base = (size_t)m * KTOT;
            *(uint32_t*)&attn16[base + col]        = hi;
            *(uint32_t*)&attn16[base + 512 + col]  = lo;
            *(uint32_t*)&attn16[base + 1024 + col] = hi;
        }
    }
}

// ---------------------------------------------------------------- launcher
extern "C" void kernel_launch(void* const* d_in, const int* in_sizes, int n_in,
                              void* d_out, int out_size) {
    const float* feat  = (const float*)d_in[0];
    const float* in_w  = (const float*)d_in[1];
    const float* in_b  = (const float*)d_in[2];
    const float* out_w = (const float*)d_in[3];
    const float* out_b = (const float*)d_in[4];
    const float* ln_g  = (const float*)d_in[5];
    const float* ln_b  = (const float*)d_in[6];
    float* out = (float*)d_out;

    __nv_bfloat16 *a16, *w16, *ow16, *attn16;
    cudaGetSymbolAddress((void**)&a16,    g_a16);
    cudaGetSymbolAddress((void**)&w16,    g_w16);
    cudaGetSymbolAddress((void**)&ow16,   g_ow16);
    cudaGetSymbolAddress((void**)&attn16, g_attn16);

    cudaFuncSetAttribute(gemm_mma<1>, cudaFuncAttributeMaxDynamicSharedMemorySize, GEMM_SMEM);
    cudaFuncSetAttribute(gemm_mma<2>, cudaFuncAttributeMaxDynamicSharedMemorySize, GEMM_SMEM);
    cudaFuncSetAttribute(attn_mma, cudaFuncAttributeMaxDynamicSharedMemorySize, ATTN_SMEM);

    // 1. LayerNorm -> [Ah|Al|Ah]
    ln_kernel<<<M_ROWS, 256>>>(feat, ln_g, ln_b);

    // 2. weight conversions -> [Wh|Wh|Wl]
    wconv_kernel<<<(QKV_N * EMBED + 255) / 256, 256>>>(in_w, w16, QKV_N * EMBED);
    wconv_kernel<<<(EMBED * EMBED + 255) / 256, 256>>>(out_w, ow16, EMBED * EMBED);

    // 3. QKV projection (HMMA, 3-term) -> split hi/lo q/k/v in [bh][w][d]
    gemm_mma<2><<<dim3(QKV_N / BN, M_ROWS / BM), 256, GEMM_SMEM>>>(
        a16, w16, in_b, nullptr, nullptr, QKV_N);

    // 4. Attention (HMMA, 3-term on QK^T and PV) -> [Ah|Al|Ah]
    attn_mma<<<dim3(W_LEN / 64, BSZ * NHEADS), 128, ATTN_SMEM>>>(attn16);

    // 5. Out projection (HMMA, 3-term) + bias + residual -> d_out
    gemm_mma<1><<<dim3(EMBED / BN, M_ROWS / BM), 256, GEMM_SMEM>>>(
        attn16, ow16, out_b, feat, out, EMBED);
}

// round 6
// speedup vs baseline: 4.2618x; 1.3158x over previous
#include <cuda_runtime.h>
#include <cuda_bf16.h>
#include <cstdint>
#include <math.h>

#define W_LEN   1024
#define BSZ     16
#define EMBED   512
#define NHEADS  8
#define HEAD_DIM 64
#define M_ROWS  (W_LEN*BSZ)      /* 16384 */
#define QKV_N   (3*EMBED)        /* 1536  */
#define KDIM    512

// ---------------- scratch (__device__ globals: no-alloc rule) ----------------
__device__ __align__(256) float g_xnorm[M_ROWS * EMBED];     // LN out (tf32-rounded)
__device__ __align__(256) float g_w32[QKV_N * EMBED];        // in_w tf32-rounded
__device__ __align__(256) float g_ow32[EMBED * EMBED];       // out_w tf32-rounded
__device__ __align__(256) float g_attnf[M_ROWS * EMBED];     // attn out (tf32-rounded)
#define BHWD (BSZ*NHEADS*W_LEN*HEAD_DIM)
__device__ __align__(256) float g_qf[BHWD];                  // Q (scaled, tf32)
__device__ __align__(256) float g_kf[BHWD];                  // K (tf32)
__device__ __align__(256) __nv_bfloat16 g_vh[BHWD];          // V (bf16 RN)

// ---------------- helpers ----------------
__device__ __forceinline__ uint32_t smem_u32(const void* p) {
    uint32_t a;
    asm("{ .reg .u64 t; cvta.to.shared.u64 t, %1; cvt.u32.u64 %0, t; }" : "=r"(a) : "l"(p));
    return a;
}
__device__ __forceinline__ float to_tf32(float x) {
    float y;
    asm("cvt.rna.tf32.f32 %0, %1;" : "=f"(y) : "f"(x));
    return y;
}
__device__ __forceinline__ void split_bf16(float v, __nv_bfloat16& h, __nv_bfloat16& l) {
    h = __float2bfloat16(v);
    l = __float2bfloat16(v - __bfloat162float(h));
}
__device__ __forceinline__ void split2(float x, float y, uint32_t& hi, uint32_t& lo) {
    __nv_bfloat16 hx, lx, hy, ly;
    split_bf16(x, hx, lx);
    split_bf16(y, hy, ly);
    __nv_bfloat162 th = __halves2bfloat162(hx, hy);
    __nv_bfloat162 tl = __halves2bfloat162(lx, ly);
    hi = *reinterpret_cast<uint32_t*>(&th);
    lo = *reinterpret_cast<uint32_t*>(&tl);
}
__device__ __forceinline__ void ldmatrix_x4(uint32_t* r, uint32_t addr) {
    asm volatile("ldmatrix.sync.aligned.m8n8.x4.shared.b16 {%0,%1,%2,%3}, [%4];"
                 : "=r"(r[0]), "=r"(r[1]), "=r"(r[2]), "=r"(r[3]) : "r"(addr));
}
__device__ __forceinline__ void ldmatrix_x4_trans(uint32_t* r, uint32_t addr) {
    asm volatile("ldmatrix.sync.aligned.m8n8.x4.trans.shared.b16 {%0,%1,%2,%3}, [%4];"
                 : "=r"(r[0]), "=r"(r[1]), "=r"(r[2]), "=r"(r[3]) : "r"(addr));
}
__device__ __forceinline__ void mma16816(float* c, const uint32_t* a, uint32_t b0, uint32_t b1) {
    asm volatile("mma.sync.aligned.m16n8k16.row.col.f32.bf16.bf16.f32 "
                 "{%0,%1,%2,%3}, {%4,%5,%6,%7}, {%8,%9}, {%0,%1,%2,%3};"
                 : "+f"(c[0]), "+f"(c[1]), "+f"(c[2]), "+f"(c[3])
                 : "r"(a[0]), "r"(a[1]), "r"(a[2]), "r"(a[3]), "r"(b0), "r"(b1));
}
__device__ __forceinline__ void mma_tf32(float* c, const uint32_t* a, uint32_t b0, uint32_t b1) {
    asm volatile("mma.sync.aligned.m16n8k8.row.col.f32.tf32.tf32.f32 "
                 "{%0,%1,%2,%3}, {%4,%5,%6,%7}, {%8,%9}, {%0,%1,%2,%3};"
                 : "+f"(c[0]), "+f"(c[1]), "+f"(c[2]), "+f"(c[3])
                 : "r"(a[0]), "r"(a[1]), "r"(a[2]), "r"(a[3]), "r"(b0), "r"(b1));
}
#define CP_ASYNC16(dst, src) \
    asm volatile("cp.async.cg.shared.global [%0], [%1], 16;" :: "r"(dst), "l"(src))
#define CP_COMMIT() asm volatile("cp.async.commit_group;" ::: "memory")
#define CP_WAIT(n)  asm volatile("cp.async.wait_group %0;" :: "n"(n) : "memory")

// fast exp on fma/alu pipes: e^x for x <= 0; rel err ~2e-6
__device__ __forceinline__ float fast_exp(float x) {
    float z = fmaxf(x * 1.442695041f, -126.0f);
    int n = __float2int_rn(z);
    float f = z - (float)n;                       // f in [-0.5, 0.5]
    float p = fmaf(f, 0.0013333558f, 0.0096181291f);
    p = fmaf(f, p, 0.0555041087f);
    p = fmaf(f, p, 0.2402265070f);
    p = fmaf(f, p, 0.6931471806f);
    p = fmaf(f, p, 1.0f);                         // 2^f
    return __int_as_float(__float_as_int(p) + (n << 23));
}

// swizzled offsets: 128B rows (8 granules) and 256B rows (16 granules)
#define SWZ128(row, g) ((row) * 128 + ((((g) ^ (row)) & 7) << 4))
#define SWZ256(row, g) ((row) * 256 + (((g) & 8) << 4) + ((((g) ^ (row)) & 7) << 4))

// ---------------------------------------------------------------- LayerNorm
__global__ void __launch_bounds__(256) ln_kernel(const float* __restrict__ feat,
                                                 const float* __restrict__ gam,
                                                 const float* __restrict__ bet) {
    int row = blockIdx.x;
    int t = threadIdx.x;
    const float2 v = ((const float2*)(feat + (size_t)row * EMBED))[t];
    __shared__ float red[8];

    float s = v.x + v.y;
    #pragma unroll
    for (int o = 16; o; o >>= 1) s += __shfl_xor_sync(0xffffffffu, s, o);
    if ((t & 31) == 0) red[t >> 5] = s;
    __syncthreads();
    float tot = 0.f;
    #pragma unroll
    for (int i = 0; i < 8; i++) tot += red[i];
    float mu = tot * (1.f / EMBED);
    __syncthreads();

    float dx = v.x - mu, dy = v.y - mu;
    float s2 = dx * dx + dy * dy;
    #pragma unroll
    for (int o = 16; o; o >>= 1) s2 += __shfl_xor_sync(0xffffffffu, s2, o);
    if ((t & 31) == 0) red[t >> 5] = s2;
    __syncthreads();
    float var = 0.f;
    #pragma unroll
    for (int i = 0; i < 8; i++) var += red[i];
    float rstd = rsqrtf(var * (1.f / EMBED) + 1e-5f);

    float2 g2 = ((const float2*)gam)[t];
    float2 b2 = ((const float2*)bet)[t];
    float ox = to_tf32(dx * rstd * g2.x + b2.x);
    float oy = to_tf32(dy * rstd * g2.y + b2.y);
    ((float2*)(g_xnorm + (size_t)row * EMBED))[t] = make_float2(ox, oy);
}

// ---------------------------------------------- weights -> tf32-rounded f32
__global__ void wtf32_kernel(const float* __restrict__ src, float* __restrict__ dst,
                             int total) {
    int i = blockIdx.x * 256 + threadIdx.x;
    if (i < total) dst[i] = to_tf32(src[i]);
}

// --------------------------------------- tf32 mma GEMM  C = A * B^T
// A [M,512] f32 K-major, B [N,512] f32 K-major. BK=32 (128B rows), 128x128 tile,
// 8 warps (2M x 4N), warp 64x32, m16n8k8 tf32, double-buffered cp.async.
// MODE 1: C = acc + bias + resid. MODE 2: QKV split-write q/k (tf32 f32), v (bf16).
#define NCHUNK (KDIM / 32)        /* 16 */
#define GEMM_SMEM 65536           /* A0 A1 B0 B1 x 16KB */

template <int MODE>
__global__ void __launch_bounds__(256, 2) gemm_tf32(const float* __restrict__ A,
                                                    const float* __restrict__ B,
                                                    const float* __restrict__ bias,
                                                    const float* __restrict__ resid,
                                                    float* __restrict__ C, int N) {
    extern __shared__ __align__(1024) char smem[];
    uint32_t sb = smem_u32(smem);
    int tid = threadIdx.x;
    int lid = tid & 31, wid = tid >> 5;
    int wm = wid & 1, wn = wid >> 1;
    int m0 = blockIdx.y * 128, n0 = blockIdx.x * 128;

    const float* Ablk = A + (size_t)m0 * KDIM;
    const float* Bblk = B + (size_t)n0 * KDIM;

    float acc[4][4][4];
    #pragma unroll
    for (int i = 0; i < 4; i++)
        #pragma unroll
        for (int j = 0; j < 4; j++)
            #pragma unroll
            for (int k = 0; k < 4; k++) acc[i][j][k] = 0.f;

    auto load_chunk = [&](int c, int s) {
        int koff = c * 32;
        uint32_t abase = sb + s * 16384;
        uint32_t bbase = sb + 32768 + s * 16384;
        #pragma unroll
        for (int i = 0; i < 4; i++) {
            int idx = tid + i * 256;
            int row = idx >> 3, g = idx & 7;
            CP_ASYNC16(abase + SWZ128(row, g), Ablk + (size_t)row * KDIM + koff + g * 4);
        }
        #pragma unroll
        for (int i = 0; i < 4; i++) {
            int idx = tid + i * 256;
            int row = idx >> 3, g = idx & 7;
            CP_ASYNC16(bbase + SWZ128(row, g), Bblk + (size_t)row * KDIM + koff + g * 4);
        }
        CP_COMMIT();
    };

    load_chunk(0, 0);

    for (int c = 0; c < NCHUNK; c++) {
        int s = c & 1;
        if (c + 1 < NCHUNK) { load_chunk(c + 1, s ^ 1); CP_WAIT(1); }
        else                { CP_WAIT(0); }
        __syncthreads();

        uint32_t abase = sb + s * 16384;
        uint32_t bbase = sb + 32768 + s * 16384;
        #pragma unroll
        for (int ks = 0; ks < 4; ks++) {          // k8 steps within BK=32
            uint32_t afr[4][4];
            #pragma unroll
            for (int mi = 0; mi < 4; mi++) {
                int row = wm * 64 + mi * 16 + ((lid >> 3) & 1) * 8 + (lid & 7);
                int g = ks * 2 + (lid >> 4);
                ldmatrix_x4(afr[mi], abase + SWZ128(row, g));
            }
            uint32_t bfr[2][4];
            #pragma unroll
            for (int nf = 0; nf < 2; nf++) {
                int row = wn * 32 + nf * 16 + ((lid >> 4) << 3) + (lid & 7);
                int g = ks * 2 + ((lid >> 3) & 1);
                ldmatrix_x4(bfr[nf], bbase + SWZ128(row, g));
            }
            #pragma unroll
            for (int mi = 0; mi < 4; mi++)
                #pragma unroll
                for (int nj = 0; nj < 4; nj++) {
                    const uint32_t* b = bfr[nj >> 1];
                    mma_tf32(acc[mi][nj], afr[mi], b[(nj & 1) * 2], b[(nj & 1) * 2 + 1]);
                }
        }
        __syncthreads();
    }

    if (MODE == 1) {
        #pragma unroll
        for (int mi = 0; mi < 4; mi++) {
            int mA = m0 + wm * 64 + mi * 16 + (lid >> 2);
            #pragma unroll
            for (int nj = 0; nj < 4; nj++) {
                int n = n0 + wn * 32 + nj * 8 + 2 * (lid & 3);
                float bx = bias[n], by = bias[n + 1];
                float2 v0 = make_float2(acc[mi][nj][0] + bx, acc[mi][nj][1] + by);
                float2 v1 = make_float2(acc[mi][nj][2] + bx, acc[mi][nj][3] + by);
                float2 r0 = *(const float2*)&resid[(size_t)mA * N + n];
                float2 r1 = *(const float2*)&resid[(size_t)(mA + 8) * N + n];
                v0.x += r0.x; v0.y += r0.y; v1.x += r1.x; v1.y += r1.y;
                *(float2*)&C[(size_t)mA * N + n] = v0;
                *(float2*)&C[(size_t)(mA + 8) * N + n] = v1;
            }
        }
    } else {
        // QKV epilogue: q/k -> tf32 f32 [bh][w][d]; v -> bf16
        #pragma unroll
        for (int mi = 0; mi < 4; mi++) {
            int mbase = m0 + wm * 64 + mi * 16 + (lid >> 2);
            #pragma unroll
            for (int nj = 0; nj < 4; nj++) {
                int n = n0 + wn * 32 + nj * 8 + 2 * (lid & 3);
                int region = n >> 9;
                int hh = (n & 511) >> 6;
                int d = n & 63;
                float bx = bias[n], by = bias[n + 1];
                #pragma unroll
                for (int rr = 0; rr < 2; rr++) {
                    int m = mbase + rr * 8;
                    int w = m >> 4, b = m & 15;
                    float vx = acc[mi][nj][rr * 2 + 0] + bx;
                    float vy = acc[mi][nj][rr * 2 + 1] + by;
                    size_t off = ((size_t)(b * 8 + hh) * W_LEN + w) * HEAD_DIM + d;
                    if (region == 0) {
                        *(float2*)&g_qf[off] =
                            make_float2(to_tf32(vx * 0.125f), to_tf32(vy * 0.125f));
                    } else if (region == 1) {
                        *(float2*)&g_kf[off] = make_float2(to_tf32(vx), to_tf32(vy));
                    } else {
                        *(__nv_bfloat162*)&g_vh[off] = __floats2bfloat162_rn(vx, vy);
                    }
                }
            }
        }
    }
}

// ------------------------------------------------------------- Attention
// 128 threads (4 warps), 64-query tile, 64-key blocks double-buffered.
// QK^T in tf32 (1-term), softmax with fast_exp, PV in bf16 2-term (exact-P split).
#define AT_Q 0                   /* 16KB fp32 64x64 */
#define AT_K 16384               /* 2 x 16KB fp32   */
#define AT_V 49152               /* 2 x 8KB bf16    */
#define ATTN_SMEM 65536

__global__ void __launch_bounds__(128) attn_kernel() {
    extern __shared__ __align__(1024) char smem[];
    uint32_t sb = smem_u32(smem);
    int tid = threadIdx.x;
    int lid = tid & 31, wid = tid >> 5;
    int bh = blockIdx.y;
    int q0 = blockIdx.x * 64;
    size_t gb = (size_t)bh * (W_LEN * HEAD_DIM);

    auto ldf32 = [&](uint32_t dstbase, const float* src, int row0) {
        #pragma unroll
        for (int i = 0; i < 8; i++) {
            int idx = tid + i * 128;
            int row = idx >> 4, g = idx & 15;
            CP_ASYNC16(dstbase + SWZ256(row, g),
                       src + gb + (size_t)(row0 + row) * HEAD_DIM + g * 4);
        }
    };
    auto ldbf16 = [&](uint32_t dstbase, const __nv_bfloat16* src, int row0) {
        #pragma unroll
        for (int i = 0; i < 4; i++) {
            int idx = tid + i * 128;
            int row = idx >> 3, g = idx & 7;
            CP_ASYNC16(dstbase + SWZ128(row, g),
                       src + gb + (size_t)(row0 + row) * HEAD_DIM + g * 8);
        }
    };

    ldf32(sb + AT_Q, g_qf, q0);
    ldf32(sb + AT_K, g_kf, 0);
    ldbf16(sb + AT_V, g_vh, 0);
    CP_COMMIT();

    float o[8][4];
    #pragma unroll
    for (int i = 0; i < 8; i++)
        #pragma unroll
        for (int j = 0; j < 4; j++) o[i][j] = 0.f;
    float mrow[2] = {-1e30f, -1e30f};
    float lrow[2] = {0.f, 0.f};

    for (int kt = 0; kt < 16; kt++) {
        int s = kt & 1;
        if (kt < 15) {
            int r0 = (kt + 1) * 64;
            ldf32(sb + AT_K + (s ^ 1) * 16384, g_kf, r0);
            ldbf16(sb + AT_V + (s ^ 1) * 8192, g_vh, r0);
            CP_COMMIT();
            CP_WAIT(1);
        } else {
            CP_WAIT(0);
        }
        __syncthreads();

        uint32_t kbase = sb + AT_K + s * 16384;
        uint32_t vbase = sb + AT_V + s * 8192;

        // ---- S = Q K^T (tf32) ----
        float sc[8][4];
        #pragma unroll
        for (int i = 0; i < 8; i++)
            #pragma unroll
            for (int j = 0; j < 4; j++) sc[i][j] = 0.f;

        #pragma unroll
        for (int s8 = 0; s8 < 8; s8++) {
            uint32_t afr[4];
            {
                int row = wid * 16 + ((lid >> 3) & 1) * 8 + (lid & 7);
                int g = s8 * 2 + (lid >> 4);
                ldmatrix_x4(afr, sb + AT_Q + SWZ256(row, g));
            }
            #pragma unroll
            for (int nf = 0; nf < 4; nf++) {
                uint32_t bfr[4];
                int row = nf * 16 + ((lid >> 4) << 3) + (lid & 7);
                int g = s8 * 2 + ((lid >> 3) & 1);
                ldmatrix_x4(bfr, kbase + SWZ256(row, g));
                mma_tf32(sc[nf * 2 + 0], afr, bfr[0], bfr[1]);
                mma_tf32(sc[nf * 2 + 1], afr, bfr[2], bfr[3]);
            }
        }

        // ---- online softmax (fast_exp, no MUFU) ----
        float mx0 = -1e30f, mx1 = -1e30f;
        #pragma unroll
        for (int j = 0; j < 8; j++) {
            mx0 = fmaxf(mx0, fmaxf(sc[j][0], sc[j][1]));
            mx1 = fmaxf(mx1, fmaxf(sc[j][2], sc[j][3]));
        }
        #pragma unroll
        for (int ofs = 1; ofs <= 2; ofs <<= 1) {
            mx0 = fmaxf(mx0, __shfl_xor_sync(0xffffffffu, mx0, ofs));
            mx1 = fmaxf(mx1, __shfl_xor_sync(0xffffffffu, mx1, ofs));
        }
        float mn0 = fmaxf(mrow[0], mx0), mn1 = fmaxf(mrow[1], mx1);
        float corr0 = fast_exp(mrow[0] - mn0), corr1 = fast_exp(mrow[1] - mn1);
        mrow[0] = mn0; mrow[1] = mn1;

        float sum0 = 0.f, sum1 = 0.f;
        #pragma unroll
        for (int j = 0; j < 8; j++) {
            sc[j][0] = fast_exp(sc[j][0] - mn0);
            sc[j][1] = fast_exp(sc[j][1] - mn0);
            sc[j][2] = fast_exp(sc[j][2] - mn1);
            sc[j][3] = fast_exp(sc[j][3] - mn1);
            sum0 += sc[j][0] + sc[j][1];
            sum1 += sc[j][2] + sc[j][3];
        }
        #pragma unroll
        for (int ofs = 1; ofs <= 2; ofs <<= 1) {
            sum0 += __shfl_xor_sync(0xffffffffu, sum0, ofs);
            sum1 += __shfl_xor_sync(0xffffffffu, sum1, ofs);
        }
        lrow[0] = lrow[0] * corr0 + sum0;
        lrow[1] = lrow[1] * corr1 + sum1;
        #pragma unroll
        for (int nd = 0; nd < 8; nd++) {
            o[nd][0] *= corr0; o[nd][1] *= corr0;
            o[nd][2] *= corr1; o[nd][3] *= corr1;
        }

        // ---- P frags (exact hi+lo bf16 split) ----
        uint32_t ph[4][4], pl[4][4];
        #pragma unroll
        for (int kc = 0; kc < 4; kc++) {
            int j0 = kc * 2, j1 = kc * 2 + 1;
            split2(sc[j0][0], sc[j0][1], ph[kc][0], pl[kc][0]);
            split2(sc[j0][2], sc[j0][3], ph[kc][1], pl[kc][1]);
            split2(sc[j1][0], sc[j1][1], ph[kc][2], pl[kc][2]);
            split2(sc[j1][2], sc[j1][3], ph[kc][3], pl[kc][3]);
        }

        // ---- O += P V (bf16, 2-term) ----
        #pragma unroll
        for (int kc = 0; kc < 4; kc++) {
            #pragma unroll
            for (int np = 0; np < 4; np++) {
                uint32_t vhf[4];
                int row = kc * 16 + (lid & 7) + ((lid >> 3) & 1) * 8;
                int c16 = np * 2 + ((lid >> 4) & 1);
                ldmatrix_x4_trans(vhf, vbase + ((row * 128) + (((c16 ^ (row & 7)) & 7) << 4)));
                #pragma unroll
                for (int t = 0; t < 2; t++) {
                    float* c = o[np * 2 + t];
                    mma16816(c, ph[kc], vhf[t * 2], vhf[t * 2 + 1]);
                    mma16816(c, pl[kc], vhf[t * 2], vhf[t * 2 + 1]);
                }
            }
        }
        __syncthreads();
    }

    // ---- epilogue: normalize, write tf32-rounded fp32 [m][E] ----
    float inv0 = 1.f / lrow[0], inv1 = 1.f / lrow[1];
    int b = bh >> 3, h = bh & 7;
    int r0 = lid >> 2, c0 = (lid & 3) * 2;
    #pragma unroll
    for (int nd = 0; nd < 8; nd++) {
        int col = h * HEAD_DIM + nd * 8 + c0;
        #pragma unroll
        for (int rr = 0; rr < 2; rr++) {
            int w = q0 + wid * 16 + r0 + rr * 8;
            int m = w * BSZ + b;
            float inv = rr ? inv1 : inv0;
            float vx = to_tf32(o[nd][rr * 2 + 0] * inv);
            float vy = to_tf32(o[nd][rr * 2 + 1] * inv);
            *(float2*)&g_attnf[(size_t)m * EMBED + col] = make_float2(vx, vy);
        }
    }
}

// ---------------------------------------------------------------- launcher
extern "C" void kernel_launch(void* const* d_in, const int* in_sizes, int n_in,
                              void* d_out, int out_size) {
    const float* feat  = (const float*)d_in[0];
    const float* in_w  = (const float*)d_in[1];
    const float* in_b  = (const float*)d_in[2];
    const float* out_w = (const float*)d_in[3];
    const float* out_b = (const float*)d_in[4];
    const float* ln_g  = (const float*)d_in[5];
    const float* ln_b  = (const float*)d_in[6];
    float* out = (float*)d_out;

    float *xnorm, *w32, *ow32, *attnf;
    cudaGetSymbolAddress((void**)&xnorm, g_xnorm);
    cudaGetSymbolAddress((void**)&w32,   g_w32);
    cudaGetSymbolAddress((void**)&ow32,  g_ow32);
    cudaGetSymbolAddress((void**)&attnf, g_attnf);

    cudaFuncSetAttribute(gemm_tf32<1>, cudaFuncAttributeMaxDynamicSharedMemorySize, GEMM_SMEM);
    cudaFuncSetAttribute(gemm_tf32<2>, cudaFuncAttributeMaxDynamicSharedMemorySize, GEMM_SMEM);
    cudaFuncSetAttribute(attn_kernel, cudaFuncAttributeMaxDynamicSharedMemorySize, ATTN_SMEM);

    // 1. LayerNorm -> tf32-rounded fp32
    ln_kernel<<<M_ROWS, 256>>>(feat, ln_g, ln_b);

    // 2. round weights to tf32
    wtf32_kernel<<<(QKV_N * EMBED + 255) / 256, 256>>>(in_w, w32, QKV_N * EMBED);
    wtf32_kernel<<<(EMBED * EMBED + 255) / 256, 256>>>(out_w, ow32, EMBED * EMBED);

    // 3. QKV projection (tf32 mma) -> q/k fp32, v bf16 in [bh][w][d]
    gemm_tf32<2><<<dim3(QKV_N / 128, M_ROWS / 128), 256, GEMM_SMEM>>>(
        xnorm, w32, in_b, nullptr, nullptr, QKV_N);

    // 4. Attention (tf32 QK, fast_exp softmax, bf16 2-term PV)
    attn_kernel<<<dim3(W_LEN / 64, BSZ * NHEADS), 128, ATTN_SMEM>>>();

    // 5. Out projection (tf32 mma) + bias + residual -> d_out
    gemm_tf32<1><<<dim3(EMBED / 128, M_ROWS / 128), 256, GEMM_SMEM>>>(
        attnf, ow32, out_b, feat, out, EMBED);
}

// round 7
// speedup vs baseline: 5.0602x; 1.1873x over previous
#include <cuda_runtime.h>
#include <cuda_bf16.h>
#include <cstdint>
#include <math.h>

#define W_LEN   1024
#define BSZ     16
#define EMBED   512
#define NHEADS  8
#define HEAD_DIM 64
#define M_ROWS  (W_LEN*BSZ)      /* 16384 */
#define QKV_N   (3*EMBED)        /* 1536  */
#define KDIM    512

// ---------------- scratch (__device__ globals: no-alloc rule) ----------------
__device__ __align__(256) __nv_bfloat16 g_xh[M_ROWS * EMBED];    // LN out bf16
__device__ __align__(256) __nv_bfloat16 g_wh[QKV_N * EMBED];     // in_w bf16
__device__ __align__(256) __nv_bfloat16 g_owh[EMBED * EMBED];    // out_w bf16
__device__ __align__(256) __nv_bfloat16 g_attnh[M_ROWS * EMBED]; // attn out bf16
#define BHWD (BSZ*NHEADS*W_LEN*HEAD_DIM)
__device__ __align__(256) float g_qf[BHWD];                      // Q (scaled, tf32)
__device__ __align__(256) float g_kf[BHWD];                      // K (tf32)
__device__ __align__(256) __nv_bfloat16 g_vh[BHWD];              // V (bf16 RN)

// ---------------- helpers ----------------
__device__ __forceinline__ uint32_t smem_u32(const void* p) {
    uint32_t a;
    asm("{ .reg .u64 t; cvta.to.shared.u64 t, %1; cvt.u32.u64 %0, t; }" : "=r"(a) : "l"(p));
    return a;
}
__device__ __forceinline__ float to_tf32(float x) {
    float y;
    asm("cvt.rna.tf32.f32 %0, %1;" : "=f"(y) : "f"(x));
    return y;
}
__device__ __forceinline__ void split_bf16(float v, __nv_bfloat16& h, __nv_bfloat16& l) {
    h = __float2bfloat16(v);
    l = __float2bfloat16(v - __bfloat162float(h));
}
__device__ __forceinline__ void split2(float x, float y, uint32_t& hi, uint32_t& lo) {
    __nv_bfloat16 hx, lx, hy, ly;
    split_bf16(x, hx, lx);
    split_bf16(y, hy, ly);
    __nv_bfloat162 th = __halves2bfloat162(hx, hy);
    __nv_bfloat162 tl = __halves2bfloat162(lx, ly);
    hi = *reinterpret_cast<uint32_t*>(&th);
    lo = *reinterpret_cast<uint32_t*>(&tl);
}
__device__ __forceinline__ void ldmatrix_x4(uint32_t* r, uint32_t addr) {
    asm volatile("ldmatrix.sync.aligned.m8n8.x4.shared.b16 {%0,%1,%2,%3}, [%4];"
                 : "=r"(r[0]), "=r"(r[1]), "=r"(r[2]), "=r"(r[3]) : "r"(addr));
}
__device__ __forceinline__ void ldmatrix_x4_trans(uint32_t* r, uint32_t addr) {
    asm volatile("ldmatrix.sync.aligned.m8n8.x4.trans.shared.b16 {%0,%1,%2,%3}, [%4];"
                 : "=r"(r[0]), "=r"(r[1]), "=r"(r[2]), "=r"(r[3]) : "r"(addr));
}
__device__ __forceinline__ void mma16816(float* c, const uint32_t* a, uint32_t b0, uint32_t b1) {
    asm volatile("mma.sync.aligned.m16n8k16.row.col.f32.bf16.bf16.f32 "
                 "{%0,%1,%2,%3}, {%4,%5,%6,%7}, {%8,%9}, {%0,%1,%2,%3};"
                 : "+f"(c[0]), "+f"(c[1]), "+f"(c[2]), "+f"(c[3])
                 : "r"(a[0]), "r"(a[1]), "r"(a[2]), "r"(a[3]), "r"(b0), "r"(b1));
}
__device__ __forceinline__ void mma_tf32(float* c, const uint32_t* a, uint32_t b0, uint32_t b1) {
    asm volatile("mma.sync.aligned.m16n8k8.row.col.f32.tf32.tf32.f32 "
                 "{%0,%1,%2,%3}, {%4,%5,%6,%7}, {%8,%9}, {%0,%1,%2,%3};"
                 : "+f"(c[0]), "+f"(c[1]), "+f"(c[2]), "+f"(c[3])
                 : "r"(a[0]), "r"(a[1]), "r"(a[2]), "r"(a[3]), "r"(b0), "r"(b1));
}
#define CP_ASYNC16(dst, src) \
    asm volatile("cp.async.cg.shared.global [%0], [%1], 16;" :: "r"(dst), "l"(src))
#define CP_COMMIT() asm volatile("cp.async.commit_group;" ::: "memory")
#define CP_WAIT(n)  asm volatile("cp.async.wait_group %0;" :: "n"(n) : "memory")

// fast exp on fma/alu pipes (x <= 0): rel err ~2e-6
__device__ __forceinline__ float fast_exp(float x) {
    float z = fmaxf(x * 1.442695041f, -126.0f);
    int n = __float2int_rn(z);
    float f = z - (float)n;
    float p = fmaf(f, 0.0013333558f, 0.0096181291f);
    p = fmaf(f, p, 0.0555041087f);
    p = fmaf(f, p, 0.2402265070f);
    p = fmaf(f, p, 0.6931471806f);
    p = fmaf(f, p, 1.0f);
    return __int_as_float(__float_as_int(p) + (n << 23));
}

#define SWZ128(row, g) ((row) * 128 + ((((g) ^ (row)) & 7) << 4))
#define SWZ256(row, g) ((row) * 256 + (((g) & 8) << 4) + ((((g) ^ (row)) & 7) << 4))

// ---------------------------------------------------------------- LayerNorm
__global__ void __launch_bounds__(256) ln_kernel(const float* __restrict__ feat,
                                                 const float* __restrict__ gam,
                                                 const float* __restrict__ bet) {
    int row = blockIdx.x;
    int t = threadIdx.x;
    const float2 v = ((const float2*)(feat + (size_t)row * EMBED))[t];
    __shared__ float red[8];

    float s = v.x + v.y;
    #pragma unroll
    for (int o = 16; o; o >>= 1) s += __shfl_xor_sync(0xffffffffu, s, o);
    if ((t & 31) == 0) red[t >> 5] = s;
    __syncthreads();
    float tot = 0.f;
    #pragma unroll
    for (int i = 0; i < 8; i++) tot += red[i];
    float mu = tot * (1.f / EMBED);
    __syncthreads();

    float dx = v.x - mu, dy = v.y - mu;
    float s2 = dx * dx + dy * dy;
    #pragma unroll
    for (int o = 16; o; o >>= 1) s2 += __shfl_xor_sync(0xffffffffu, s2, o);
    if ((t & 31) == 0) red[t >> 5] = s2;
    __syncthreads();
    float var = 0.f;
    #pragma unroll
    for (int i = 0; i < 8; i++) var += red[i];
    float rstd = rsqrtf(var * (1.f / EMBED) + 1e-5f);

    float2 g2 = ((const float2*)gam)[t];
    float2 b2 = ((const float2*)bet)[t];
    float ox = dx * rstd * g2.x + b2.x;
    float oy = dy * rstd * g2.y + b2.y;
    *(__nv_bfloat162*)&g_xh[(size_t)row * EMBED + 2 * t] = __floats2bfloat162_rn(ox, oy);
}

// ---------------------------------------------- weights fp32 -> bf16
__global__ void wconv_kernel(const float* __restrict__ src, __nv_bfloat16* __restrict__ dst,
                             int total) {
    int i = blockIdx.x * 256 + threadIdx.x;
    if (i < total) dst[i] = __float2bfloat16(src[i]);
}

// --------------------------------------- bf16 mma GEMM  C = A * B^T
// A [M,512] bf16 K-major, B [N,512] bf16 K-major. BK=64 (128B rows), 128x128
// tile, 8 warps (2M x 4N), warp 64x32, m16n8k16, double-buffered cp.async.
// MODE 1: C = acc + bias + resid (fp32). MODE 2: QKV split-write.
#define NCHUNK (KDIM / 64)        /* 8 */
#define ABUF 16384
#define GEMM_SMEM (4 * ABUF)      /* 64KB */

template <int MODE>
__global__ void __launch_bounds__(256, 2) gemm_mma(const __nv_bfloat16* __restrict__ A,
                                                   const __nv_bfloat16* __restrict__ B,
                                                   const float* __restrict__ bias,
                                                   const float* __restrict__ resid,
                                                   float* __restrict__ C, int N) {
    extern __shared__ __align__(1024) char smem[];
    uint32_t sb = smem_u32(smem);
    int tid = threadIdx.x;
    int lid = tid & 31, wid = tid >> 5;
    int wm = wid & 1, wn = wid >> 1;
    int m0 = blockIdx.y * 128, n0 = blockIdx.x * 128;

    const __nv_bfloat16* Ablk = A + (size_t)m0 * KDIM;
    const __nv_bfloat16* Bblk = B + (size_t)n0 * KDIM;

    float acc[4][4][4];
    #pragma unroll
    for (int i = 0; i < 4; i++)
        #pragma unroll
        for (int j = 0; j < 4; j++)
            #pragma unroll
            for (int k = 0; k < 4; k++) acc[i][j][k] = 0.f;

    auto load_chunk = [&](int c, int s) {
        int koff = c * 64;
        uint32_t abase = sb + s * ABUF;
        uint32_t bbase = sb + 2 * ABUF + s * ABUF;
        #pragma unroll
        for (int i = 0; i < 4; i++) {
            int idx = tid + i * 256;
            int row = idx >> 3, g = idx & 7;
            CP_ASYNC16(abase + SWZ128(row, g), Ablk + (size_t)row * KDIM + koff + g * 8);
        }
        #pragma unroll
        for (int i = 0; i < 4; i++) {
            int idx = tid + i * 256;
            int row = idx >> 3, g = idx & 7;
            CP_ASYNC16(bbase + SWZ128(row, g), Bblk + (size_t)row * KDIM + koff + g * 8);
        }
        CP_COMMIT();
    };

    load_chunk(0, 0);

    for (int c = 0; c < NCHUNK; c++) {
        int s = c & 1;
        if (c + 1 < NCHUNK) { load_chunk(c + 1, s ^ 1); CP_WAIT(1); }
        else                { CP_WAIT(0); }
        __syncthreads();

        uint32_t abase = sb + s * ABUF;
        uint32_t bbase = sb + 2 * ABUF + s * ABUF;
        #pragma unroll
        for (int ks = 0; ks < 4; ks++) {          // 4 k16-steps per BK=64
            uint32_t afr[4][4];
            #pragma unroll
            for (int mi = 0; mi < 4; mi++) {
                int row = wm * 64 + mi * 16 + (lid & 15);
                int g = ks * 2 + (lid >> 4);
                ldmatrix_x4(afr[mi], abase + SWZ128(row, g));
            }
            uint32_t bfr[2][4];
            #pragma unroll
            for (int nf = 0; nf < 2; nf++) {
                int row = wn * 32 + nf * 16 + (lid & 7) + ((lid & 16) >> 1);
                int g = ks * 2 + ((lid & 8) >> 3);
                ldmatrix_x4(bfr[nf], bbase + SWZ128(row, g));
            }
            #pragma unroll
            for (int mi = 0; mi < 4; mi++)
                #pragma unroll
                for (int nj = 0; nj < 4; nj++) {
                    const uint32_t* b = bfr[nj >> 1];
                    mma16816(acc[mi][nj], afr[mi], b[(nj & 1) * 2], b[(nj & 1) * 2 + 1]);
                }
        }
        __syncthreads();
    }

    if (MODE == 1) {
        #pragma unroll
        for (int mi = 0; mi < 4; mi++) {
            int mA = m0 + wm * 64 + mi * 16 + (lid >> 2);
            #pragma unroll
            for (int nj = 0; nj < 4; nj++) {
                int n = n0 + wn * 32 + nj * 8 + 2 * (lid & 3);
                float bx = bias[n], by = bias[n + 1];
                float2 v0 = make_float2(acc[mi][nj][0] + bx, acc[mi][nj][1] + by);
                float2 v1 = make_float2(acc[mi][nj][2] + bx, acc[mi][nj][3] + by);
                float2 r0 = *(const float2*)&resid[(size_t)mA * N + n];
                float2 r1 = *(const float2*)&resid[(size_t)(mA + 8) * N + n];
                v0.x += r0.x; v0.y += r0.y; v1.x += r1.x; v1.y += r1.y;
                *(float2*)&C[(size_t)mA * N + n] = v0;
                *(float2*)&C[(size_t)(mA + 8) * N + n] = v1;
            }
        }
    } else {
        // QKV epilogue: q/k -> tf32 f32 [bh][w][d]; v -> bf16
        #pragma unroll
        for (int mi = 0; mi < 4; mi++) {
            int mbase = m0 + wm * 64 + mi * 16 + (lid >> 2);
            #pragma unroll
            for (int nj = 0; nj < 4; nj++) {
                int n = n0 + wn * 32 + nj * 8 + 2 * (lid & 3);
                int region = n >> 9;
                int hh = (n & 511) >> 6;
                int d = n & 63;
                float bx = bias[n], by = bias[n + 1];
                #pragma unroll
                for (int rr = 0; rr < 2; rr++) {
                    int m = mbase + rr * 8;
                    int w = m >> 4, b = m & 15;
                    float vx = acc[mi][nj][rr * 2 + 0] + bx;
                    float vy = acc[mi][nj][rr * 2 + 1] + by;
                    size_t off = ((size_t)(b * 8 + hh) * W_LEN + w) * HEAD_DIM + d;
                    if (region == 0) {
                        *(float2*)&g_qf[off] =
                            make_float2(to_tf32(vx * 0.125f), to_tf32(vy * 0.125f));
                    } else if (region == 1) {
                        *(float2*)&g_kf[off] = make_float2(to_tf32(vx), to_tf32(vy));
                    } else {
                        *(__nv_bfloat162*)&g_vh[off] = __floats2bfloat162_rn(vx, vy);
                    }
                }
            }
        }
    }
}

// ------------------------------------------------------------- Attention
// 256 threads (8 warps), 128-query tile, 64-key blocks double-buffered.
// QK^T tf32, fast_exp softmax, PV bf16 2-term (exact P split). Out -> bf16.
#define AT_Q 0                   /* 32KB fp32 128x64 */
#define AT_K 32768               /* 2 x 16KB fp32    */
#define AT_V 65536               /* 2 x 8KB bf16     */
#define ATTN_SMEM 81920

__global__ void __launch_bounds__(256) attn_kernel() {
    extern __shared__ __align__(1024) char smem[];
    uint32_t sb = smem_u32(smem);
    int tid = threadIdx.x;
    int lid = tid & 31, wid = tid >> 5;
    int bh = blockIdx.y;
    int q0 = blockIdx.x * 128;
    size_t gb = (size_t)bh * (W_LEN * HEAD_DIM);

    // Q: 128 rows x 16 granules; K: 64 x 16; V: 64 x 8
    auto ldQ = [&](uint32_t dstbase, const float* src, int row0) {
        #pragma unroll
        for (int i = 0; i < 8; i++) {
            int idx = tid + i * 256;
            int row = idx >> 4, g = idx & 15;
            CP_ASYNC16(dstbase + SWZ256(row, g),
                       src + gb + (size_t)(row0 + row) * HEAD_DIM + g * 4);
        }
    };
    auto ldK = [&](uint32_t dstbase, const float* src, int row0) {
        #pragma unroll
        for (int i = 0; i < 4; i++) {
            int idx = tid + i * 256;
            int row = idx >> 4, g = idx & 15;
            CP_ASYNC16(dstbase + SWZ256(row, g),
                       src + gb + (size_t)(row0 + row) * HEAD_DIM + g * 4);
        }
    };
    auto ldV = [&](uint32_t dstbase, const __nv_bfloat16* src, int row0) {
        #pragma unroll
        for (int i = 0; i < 2; i++) {
            int idx = tid + i * 256;
            int row = idx >> 3, g = idx & 7;
            CP_ASYNC16(dstbase + SWZ128(row, g),
                       src + gb + (size_t)(row0 + row) * HEAD_DIM + g * 8);
        }
    };

    ldQ(sb + AT_Q, g_qf, q0);
    ldK(sb + AT_K, g_kf, 0);
    ldV(sb + AT_V, g_vh, 0);
    CP_COMMIT();

    float o[8][4];
    #pragma unroll
    for (int i = 0; i < 8; i++)
        #pragma unroll
        for (int j = 0; j < 4; j++) o[i][j] = 0.f;
    float mrow[2] = {-1e30f, -1e30f};
    float lrow[2] = {0.f, 0.f};

    for (int kt = 0; kt < 16; kt++) {
        int s = kt & 1;
        if (kt < 15) {
            int r0 = (kt + 1) * 64;
            ldK(sb + AT_K + (s ^ 1) * 16384, g_kf, r0);
            ldV(sb + AT_V + (s ^ 1) * 8192, g_vh, r0);
            CP_COMMIT();
            CP_WAIT(1);
        } else {
            CP_WAIT(0);
        }
        __syncthreads();

        uint32_t kbase = sb + AT_K + s * 16384;
        uint32_t vbase = sb + AT_V + s * 8192;

        // ---- S = Q K^T (tf32), warp handles rows wid*16..+15 x all 64 keys
        float sc[8][4];
        #pragma unroll
        for (int i = 0; i < 8; i++)
            #pragma unroll
            for (int j = 0; j < 4; j++) sc[i][j] = 0.f;

        #pragma unroll
        for (int s8 = 0; s8 < 8; s8++) {
            uint32_t afr[4];
            {
                int row = wid * 16 + ((lid >> 3) & 1) * 8 + (lid & 7);
                int g = s8 * 2 + (lid >> 4);
                ldmatrix_x4(afr, sb + AT_Q + SWZ256(row, g));
            }
            #pragma unroll
            for (int nf = 0; nf < 4; nf++) {
                uint32_t bfr[4];
                int row = nf * 16 + ((lid >> 4) << 3) + (lid & 7);
                int g = s8 * 2 + ((lid >> 3) & 1);
                ldmatrix_x4(bfr, kbase + SWZ256(row, g));
                mma_tf32(sc[nf * 2 + 0], afr, bfr[0], bfr[1]);
                mma_tf32(sc[nf * 2 + 1], afr, bfr[2], bfr[3]);
            }
        }

        // ---- online softmax ----
        float mx0 = -1e30f, mx1 = -1e30f;
        #pragma unroll
        for (int j = 0; j < 8; j++) {
            mx0 = fmaxf(mx0, fmaxf(sc[j][0], sc[j][1]));
            mx1 = fmaxf(mx1, fmaxf(sc[j][2], sc[j][3]));
        }
        #pragma unroll
        for (int ofs = 1; ofs <= 2; ofs <<= 1) {
            mx0 = fmaxf(mx0, __shfl_xor_sync(0xffffffffu, mx0, ofs));
            mx1 = fmaxf(mx1, __shfl_xor_sync(0xffffffffu, mx1, ofs));
        }
        float mn0 = fmaxf(mrow[0], mx0), mn1 = fmaxf(mrow[1], mx1);
        float corr0 = fast_exp(mrow[0] - mn0), corr1 = fast_exp(mrow[1] - mn1);
        mrow[0] = mn0; mrow[1] = mn1;

        float sum0 = 0.f, sum1 = 0.f;
        #pragma unroll
        for (int j = 0; j < 8; j++) {
            sc[j][0] = fast_exp(sc[j][0] - mn0);
            sc[j][1] = fast_exp(sc[j][1] - mn0);
            sc[j][2] = fast_exp(sc[j][2] - mn1);
            sc[j][3] = fast_exp(sc[j][3] - mn1);
            sum0 += sc[j][0] + sc[j][1];
            sum1 += sc[j][2] + sc[j][3];
        }
        #pragma unroll
        for (int ofs = 1; ofs <= 2; ofs <<= 1) {
            sum0 += __shfl_xor_sync(0xffffffffu, sum0, ofs);
            sum1 += __shfl_xor_sync(0xffffffffu, sum1, ofs);
        }
        lrow[0] = lrow[0] * corr0 + sum0;
        lrow[1] = lrow[1] * corr1 + sum1;
        #pragma unroll
        for (int nd = 0; nd < 8; nd++) {
            o[nd][0] *= corr0; o[nd][1] *= corr0;
            o[nd][2] *= corr1; o[nd][3] *= corr1;
        }

        // ---- P frags (exact hi+lo bf16 split) ----
        uint32_t ph[4][4], pl[4][4];
        #pragma unroll
        for (int kc = 0; kc < 4; kc++) {
            int j0 = kc * 2, j1 = kc * 2 + 1;
            split2(sc[j0][0], sc[j0][1], ph[kc][0], pl[kc][0]);
            split2(sc[j0][2], sc[j0][3], ph[kc][1], pl[kc][1]);
            split2(sc[j1][0], sc[j1][1], ph[kc][2], pl[kc][2]);
            split2(sc[j1][2], sc[j1][3], ph[kc][3], pl[kc][3]);
        }

        // ---- O += P V (bf16, 2-term) ----
        #pragma unroll
        for (int kc = 0; kc < 4; kc++) {
            #pragma unroll
            for (int np = 0; np < 4; np++) {
                uint32_t vhf[4];
                int row = kc * 16 + (lid & 7) + ((lid >> 3) & 1) * 8;
                int c16 = np * 2 + ((lid >> 4) & 1);
                ldmatrix_x4_trans(vhf, vbase + ((row * 128) + (((c16 ^ (row & 7)) & 7) << 4)));
                #pragma unroll
                for (int t = 0; t < 2; t++) {
                    float* c = o[np * 2 + t];
                    mma16816(c, ph[kc], vhf[t * 2], vhf[t * 2 + 1]);
                    mma16816(c, pl[kc], vhf[t * 2], vhf[t * 2 + 1]);
                }
            }
        }
        __syncthreads();
    }

    // ---- epilogue: normalize, write bf16 [m][E] ----
    float inv0 = 1.f / lrow[0], inv1 = 1.f / lrow[1];
    int b = bh >> 3, h = bh & 7;
    int r0 = lid >> 2, c0 = (lid & 3) * 2;
    #pragma unroll
    for (int nd = 0; nd < 8; nd++) {
        int col = h * HEAD_DIM + nd * 8 + c0;
        #pragma unroll
        for (int rr = 0; rr < 2; rr++) {
            int w = q0 + wid * 16 + r0 + rr * 8;
            int m = w * BSZ + b;
            float inv = rr ? inv1 : inv0;
            float vx = o[nd][rr * 2 + 0] * inv;
            float vy = o[nd][rr * 2 + 1] * inv;
            *(__nv_bfloat162*)&g_attnh[(size_t)m * EMBED + col] = __floats2bfloat162_rn(vx, vy);
        }
    }
}

// ---------------------------------------------------------------- launcher
extern "C" void kernel_launch(void* const* d_in, const int* in_sizes, int n_in,
                              void* d_out, int out_size) {
    const float* feat  = (const float*)d_in[0];
    const float* in_w  = (const float*)d_in[1];
    const float* in_b  = (const float*)d_in[2];
    const float* out_w = (const float*)d_in[3];
    const float* out_b = (const float*)d_in[4];
    const float* ln_g  = (const float*)d_in[5];
    const float* ln_b  = (const float*)d_in[6];
    float* out = (float*)d_out;

    __nv_bfloat16 *xh, *wh, *owh, *attnh;
    cudaGetSymbolAddress((void**)&xh,    g_xh);
    cudaGetSymbolAddress((void**)&wh,    g_wh);
    cudaGetSymbolAddress((void**)&owh,   g_owh);
    cudaGetSymbolAddress((void**)&attnh, g_attnh);

    cudaFuncSetAttribute(gemm_mma<1>, cudaFuncAttributeMaxDynamicSharedMemorySize, GEMM_SMEM);
    cudaFuncSetAttribute(gemm_mma<2>, cudaFuncAttributeMaxDynamicSharedMemorySize, GEMM_SMEM);
    cudaFuncSetAttribute(attn_kernel, cudaFuncAttributeMaxDynamicSharedMemorySize, ATTN_SMEM);

    // 1. LayerNorm -> bf16
    ln_kernel<<<M_ROWS, 256>>>(feat, ln_g, ln_b);

    // 2. weights -> bf16
    wconv_kernel<<<(QKV_N * EMBED + 255) / 256, 256>>>(in_w, wh, QKV_N * EMBED);
    wconv_kernel<<<(EMBED * EMBED + 255) / 256, 256>>>(out_w, owh, EMBED * EMBED);

    // 3. QKV projection (bf16 mma) -> q/k tf32 f32, v bf16 in [bh][w][d]
    gemm_mma<2><<<dim3(QKV_N / 128, M_ROWS / 128), 256, GEMM_SMEM>>>(
        xh, wh, in_b, nullptr, nullptr, QKV_N);

    // 4. Attention (tf32 QK, fast_exp, bf16 2-term PV) -> bf16
    attn_kernel<<<dim3(W_LEN / 128, BSZ * NHEADS), 256, ATTN_SMEM>>>();

    // 5. Out projection (bf16 mma) + bias + residual -> d_out
    gemm_mma<1><<<dim3(EMBED / 128, M_ROWS / 128), 256, GEMM_SMEM>>>(
        attnh, owh, out_b, feat, out, EMBED);
}

// round 9
// speedup vs baseline: 6.5995x; 1.3042x over previous
#include <cuda_runtime.h>
#include <cuda_bf16.h>
#include <cstdint>
#include <math.h>

#define W_LEN   1024
#define BSZ     16
#define EMBED   512
#define NHEADS  8
#define HEAD_DIM 64
#define M_ROWS  (W_LEN*BSZ)      /* 16384 */
#define QKV_N   (3*EMBED)        /* 1536  */
#define KDIM    512

// ---------------- scratch (__device__ globals: no-alloc rule) ----------------
__device__ __align__(256) __nv_bfloat16 g_xh[M_ROWS * EMBED];    // LN out bf16
__device__ __align__(256) __nv_bfloat16 g_wh[QKV_N * EMBED];     // in_w bf16
__device__ __align__(256) __nv_bfloat16 g_owh[EMBED * EMBED];    // out_w bf16
__device__ __align__(256) __nv_bfloat16 g_attnh[M_ROWS * EMBED]; // attn out bf16
#define BHWD (BSZ*NHEADS*W_LEN*HEAD_DIM)
__device__ __align__(256) float g_qf[BHWD];                      // Q (scaled, tf32)
__device__ __align__(256) float g_kf[BHWD];                      // K (tf32)
__device__ __align__(256) __nv_bfloat16 g_vh[BHWD];              // V (bf16 RN)

// ---------------- helpers ----------------
__device__ __forceinline__ uint32_t smem_u32(const void* p) {
    uint32_t a;
    asm("{ .reg .u64 t; cvta.to.shared.u64 t, %1; cvt.u32.u64 %0, t; }" : "=r"(a) : "l"(p));
    return a;
}
__device__ __forceinline__ float to_tf32(float x) {
    float y;
    asm("cvt.rna.tf32.f32 %0, %1;" : "=f"(y) : "f"(x));
    return y;
}
__device__ __forceinline__ uint32_t pack_bf16(float x, float y) {
    __nv_bfloat162 t = __floats2bfloat162_rn(x, y);
    return *reinterpret_cast<uint32_t*>(&t);
}
__device__ __forceinline__ void ldmatrix_x4(uint32_t* r, uint32_t addr) {
    asm volatile("ldmatrix.sync.aligned.m8n8.x4.shared.b16 {%0,%1,%2,%3}, [%4];"
                 : "=r"(r[0]), "=r"(r[1]), "=r"(r[2]), "=r"(r[3]) : "r"(addr));
}
__device__ __forceinline__ void ldmatrix_x4_trans(uint32_t* r, uint32_t addr) {
    asm volatile("ldmatrix.sync.aligned.m8n8.x4.trans.shared.b16 {%0,%1,%2,%3}, [%4];"
                 : "=r"(r[0]), "=r"(r[1]), "=r"(r[2]), "=r"(r[3]) : "r"(addr));
}
__device__ __forceinline__ void mma16816(float* c, const uint32_t* a, uint32_t b0, uint32_t b1) {
    asm volatile("mma.sync.aligned.m16n8k16.row.col.f32.bf16.bf16.f32 "
                 "{%0,%1,%2,%3}, {%4,%5,%6,%7}, {%8,%9}, {%0,%1,%2,%3};"
                 : "+f"(c[0]), "+f"(c[1]), "+f"(c[2]), "+f"(c[3])
                 : "r"(a[0]), "r"(a[1]), "r"(a[2]), "r"(a[3]), "r"(b0), "r"(b1));
}
__device__ __forceinline__ void mma_tf32(float* c, const uint32_t* a, uint32_t b0, uint32_t b1) {
    asm volatile("mma.sync.aligned.m16n8k8.row.col.f32.tf32.tf32.f32 "
                 "{%0,%1,%2,%3}, {%4,%5,%6,%7}, {%8,%9}, {%0,%1,%2,%3};"
                 : "+f"(c[0]), "+f"(c[1]), "+f"(c[2]), "+f"(c[3])
                 : "r"(a[0]), "r"(a[1]), "r"(a[2]), "r"(a[3]), "r"(b0), "r"(b1));
}
#define CP_ASYNC16(dst, src) \
    asm volatile("cp.async.cg.shared.global [%0], [%1], 16;" :: "r"(dst), "l"(src))
#define CP_COMMIT() asm volatile("cp.async.commit_group;" ::: "memory")
#define CP_WAIT(n)  asm volatile("cp.async.wait_group %0;" :: "n"(n) : "memory")

#define SWZ128(row, g) ((row) * 128 + ((((g) ^ (row)) & 7) << 4))
#define SWZ256(row, g) ((row) * 256 + (((g) & 8) << 4) + ((((g) ^ (row)) & 7) << 4))

// ---------------------------------------------------------------- LayerNorm
__global__ void __launch_bounds__(256) ln_kernel(const float* __restrict__ feat,
                                                 const float* __restrict__ gam,
                                                 const float* __restrict__ bet) {
    int row = blockIdx.x;
    int t = threadIdx.x;
    const float2 v = ((const float2*)(feat + (size_t)row * EMBED))[t];
    __shared__ float red[8];

    float s = v.x + v.y;
    #pragma unroll
    for (int o = 16; o; o >>= 1) s += __shfl_xor_sync(0xffffffffu, s, o);
    if ((t & 31) == 0) red[t >> 5] = s;
    __syncthreads();
    float tot = 0.f;
    #pragma unroll
    for (int i = 0; i < 8; i++) tot += red[i];
    float mu = tot * (1.f / EMBED);
    __syncthreads();

    float dx = v.x - mu, dy = v.y - mu;
    float s2 = dx * dx + dy * dy;
    #pragma unroll
    for (int o = 16; o; o >>= 1) s2 += __shfl_xor_sync(0xffffffffu, s2, o);
    if ((t & 31) == 0) red[t >> 5] = s2;
    __syncthreads();
    float var = 0.f;
    #pragma unroll
    for (int i = 0; i < 8; i++) var += red[i];
    float rstd = rsqrtf(var * (1.f / EMBED) + 1e-5f);

    float2 g2 = ((const float2*)gam)[t];
    float2 b2 = ((const float2*)bet)[t];
    float ox = dx * rstd * g2.x + b2.x;
    float oy = dy * rstd * g2.y + b2.y;
    *(__nv_bfloat162*)&g_xh[(size_t)row * EMBED + 2 * t] = __floats2bfloat162_rn(ox, oy);
}

// ---------------------------------------------- weights fp32 -> bf16
__global__ void wconv_kernel(const float* __restrict__ src, __nv_bfloat16* __restrict__ dst,
                             int total) {
    int i = blockIdx.x * 256 + threadIdx.x;
    if (i < total) dst[i] = __float2bfloat16(src[i]);
}

// --------------------------------------- bf16 mma GEMM  C = A * B^T
// MODE 1: C = acc + bias + resid (fp32). MODE 2: QKV split-write.
#define NCHUNK (KDIM / 64)        /* 8 */
#define ABUF 16384
#define GEMM_SMEM (4 * ABUF)      /* 64KB */

template <int MODE>
__global__ void __launch_bounds__(256, 2) gemm_mma(const __nv_bfloat16* __restrict__ A,
                                                   const __nv_bfloat16* __restrict__ B,
                                                   const float* __restrict__ bias,
                                                   const float* __restrict__ resid,
                                                   float* __restrict__ C, int N) {
    extern __shared__ __align__(1024) char smem[];
    uint32_t sb = smem_u32(smem);
    int tid = threadIdx.x;
    int lid = tid & 31, wid = tid >> 5;
    int wm = wid & 1, wn = wid >> 1;
    int m0 = blockIdx.y * 128, n0 = blockIdx.x * 128;

    const __nv_bfloat16* Ablk = A + (size_t)m0 * KDIM;
    const __nv_bfloat16* Bblk = B + (size_t)n0 * KDIM;

    float acc[4][4][4];
    #pragma unroll
    for (int i = 0; i < 4; i++)
        #pragma unroll
        for (int j = 0; j < 4; j++)
            #pragma unroll
            for (int k = 0; k < 4; k++) acc[i][j][k] = 0.f;

    auto load_chunk = [&](int c, int s) {
        int koff = c * 64;
        uint32_t abase = sb + s * ABUF;
        uint32_t bbase = sb + 2 * ABUF + s * ABUF;
        #pragma unroll
        for (int i = 0; i < 4; i++) {
            int idx = tid + i * 256;
            int row = idx >> 3, g = idx & 7;
            CP_ASYNC16(abase + SWZ128(row, g), Ablk + (size_t)row * KDIM + koff + g * 8);
        }
        #pragma unroll
        for (int i = 0; i < 4; i++) {
            int idx = tid + i * 256;
            int row = idx >> 3, g = idx & 7;
            CP_ASYNC16(bbase + SWZ128(row, g), Bblk + (size_t)row * KDIM + koff + g * 8);
        }
        CP_COMMIT();
    };

    load_chunk(0, 0);

    for (int c = 0; c < NCHUNK; c++) {
        int s = c & 1;
        if (c + 1 < NCHUNK) { load_chunk(c + 1, s ^ 1); CP_WAIT(1); }
        else                { CP_WAIT(0); }
        __syncthreads();

        uint32_t abase = sb + s * ABUF;
        uint32_t bbase = sb + 2 * ABUF + s * ABUF;
        #pragma unroll
        for (int ks = 0; ks < 4; ks++) {
            uint32_t afr[4][4];
            #pragma unroll
            for (int mi = 0; mi < 4; mi++) {
                int row = wm * 64 + mi * 16 + (lid & 15);
                int g = ks * 2 + (lid >> 4);
                ldmatrix_x4(afr[mi], abase + SWZ128(row, g));
            }
            uint32_t bfr[2][4];
            #pragma unroll
            for (int nf = 0; nf < 2; nf++) {
                int row = wn * 32 + nf * 16 + (lid & 7) + ((lid & 16) >> 1);
                int g = ks * 2 + ((lid & 8) >> 3);
                ldmatrix_x4(bfr[nf], bbase + SWZ128(row, g));
            }
            #pragma unroll
            for (int mi = 0; mi < 4; mi++)
                #pragma unroll
                for (int nj = 0; nj < 4; nj++) {
                    const uint32_t* b = bfr[nj >> 1];
                    mma16816(acc[mi][nj], afr[mi], b[(nj & 1) * 2], b[(nj & 1) * 2 + 1]);
                }
        }
        __syncthreads();
    }

    if (MODE == 1) {
        #pragma unroll
        for (int mi = 0; mi < 4; mi++) {
            int mA = m0 + wm * 64 + mi * 16 + (lid >> 2);
            #pragma unroll
            for (int nj = 0; nj < 4; nj++) {
                int n = n0 + wn * 32 + nj * 8 + 2 * (lid & 3);
                float bx = bias[n], by = bias[n + 1];
                float2 v0 = make_float2(acc[mi][nj][0] + bx, acc[mi][nj][1] + by);
                float2 v1 = make_float2(acc[mi][nj][2] + bx, acc[mi][nj][3] + by);
                float2 r0 = *(const float2*)&resid[(size_t)mA * N + n];
                float2 r1 = *(const float2*)&resid[(size_t)(mA + 8) * N + n];
                v0.x += r0.x; v0.y += r0.y; v1.x += r1.x; v1.y += r1.y;
                *(float2*)&C[(size_t)mA * N + n] = v0;
                *(float2*)&C[(size_t)(mA + 8) * N + n] = v1;
            }
        }
    } else {
        #pragma unroll
        for (int mi = 0; mi < 4; mi++) {
            int mbase = m0 + wm * 64 + mi * 16 + (lid >> 2);
            #pragma unroll
            for (int nj = 0; nj < 4; nj++) {
                int n = n0 + wn * 32 + nj * 8 + 2 * (lid & 3);
                int region = n >> 9;
                int hh = (n & 511) >> 6;
                int d = n & 63;
                float bx = bias[n], by = bias[n + 1];
                #pragma unroll
                for (int rr = 0; rr < 2; rr++) {
                    int m = mbase + rr * 8;
                    int w = m >> 4, b = m & 15;
                    float vx = acc[mi][nj][rr * 2 + 0] + bx;
                    float vy = acc[mi][nj][rr * 2 + 1] + by;
                    size_t off = ((size_t)(b * 8 + hh) * W_LEN + w) * HEAD_DIM + d;
                    if (region == 0) {
                        *(float2*)&g_qf[off] =
                            make_float2(to_tf32(vx * 0.125f), to_tf32(vy * 0.125f));
                    } else if (region == 1) {
                        *(float2*)&g_kf[off] = make_float2(to_tf32(vx), to_tf32(vy));
                    } else {
                        *(__nv_bfloat162*)&g_vh[off] = __floats2bfloat162_rn(vx, vy);
                    }
                }
            }
        }
    }
}

// ------------------------------------------------------------- Attention
// 256 threads (8 warps), 128-query tile, 64-key blocks double-buffered.
// QK^T tf32, __expf (MUFU) softmax, PV bf16 1-term. 2 CTAs/SM.
#define AT_Q 0                   /* 32KB fp32 128x64 */
#define AT_K 32768               /* 2 x 16KB fp32    */
#define AT_V 65536               /* 2 x 8KB bf16     */
#define ATTN_SMEM 81920

__global__ void __launch_bounds__(256, 2) attn_kernel() {
    extern __shared__ __align__(1024) char smem[];
    uint32_t sb = smem_u32(smem);
    int tid = threadIdx.x;
    int lid = tid & 31, wid = tid >> 5;
    int bh = blockIdx.y;
    int q0 = blockIdx.x * 128;
    size_t gb = (size_t)bh * (W_LEN * HEAD_DIM);

    auto ldQ = [&](uint32_t dstbase, const float* src, int row0) {
        #pragma unroll
        for (int i = 0; i < 8; i++) {
            int idx = tid + i * 256;
            int row = idx >> 4, g = idx & 15;
            CP_ASYNC16(dstbase + SWZ256(row, g),
                       src + gb + (size_t)(row0 + row) * HEAD_DIM + g * 4);
        }
    };
    auto ldK = [&](uint32_t dstbase, const float* src, int row0) {
        #pragma unroll
        for (int i = 0; i < 4; i++) {
            int idx = tid + i * 256;
            int row = idx >> 4, g = idx & 15;
            CP_ASYNC16(dstbase + SWZ256(row, g),
                       src + gb + (size_t)(row0 + row) * HEAD_DIM + g * 4);
        }
    };
    auto ldV = [&](uint32_t dstbase, const __nv_bfloat16* src, int row0) {
        #pragma unroll
        for (int i = 0; i < 2; i++) {
            int idx = tid + i * 256;
            int row = idx >> 3, g = idx & 7;
            CP_ASYNC16(dstbase + SWZ128(row, g),
                       src + gb + (size_t)(row0 + row) * HEAD_DIM + g * 8);
        }
    };

    ldQ(sb + AT_Q, g_qf, q0);
    ldK(sb + AT_K, g_kf, 0);
    ldV(sb + AT_V, g_vh, 0);
    CP_COMMIT();

    float o[8][4];
    #pragma unroll
    for (int i = 0; i < 8; i++)
        #pragma unroll
        for (int j = 0; j < 4; j++) o[i][j] = 0.f;
    float mrow[2] = {-1e30f, -1e30f};
    float lrow[2] = {0.f, 0.f};

    for (int kt = 0; kt < 16; kt++) {
        int s = kt & 1;
        if (kt < 15) {
            int r0 = (kt + 1) * 64;
            ldK(sb + AT_K + (s ^ 1) * 16384, g_kf, r0);
            ldV(sb + AT_V + (s ^ 1) * 8192, g_vh, r0);
            CP_COMMIT();
            CP_WAIT(1);
        } else {
            CP_WAIT(0);
        }
        __syncthreads();

        uint32_t kbase = sb + AT_K + s * 16384;
        uint32_t vbase = sb + AT_V + s * 8192;

        // ---- S = Q K^T (tf32) ----
        float sc[8][4];
        #pragma unroll
        for (int i = 0; i < 8; i++)
            #pragma unroll
            for (int j = 0; j < 4; j++) sc[i][j] = 0.f;

        #pragma unroll
        for (int s8 = 0; s8 < 8; s8++) {
            uint32_t afr[4];
            {
                int row = wid * 16 + ((lid >> 3) & 1) * 8 + (lid & 7);
                int g = s8 * 2 + (lid >> 4);
                ldmatrix_x4(afr, sb + AT_Q + SWZ256(row, g));
            }
            #pragma unroll
            for (int nf = 0; nf < 4; nf++) {
                uint32_t bfr[4];
                int row = nf * 16 + ((lid >> 4) << 3) + (lid & 7);
                int g = s8 * 2 + ((lid >> 3) & 1);
                ldmatrix_x4(bfr, kbase + SWZ256(row, g));
                mma_tf32(sc[nf * 2 + 0], afr, bfr[0], bfr[1]);
                mma_tf32(sc[nf * 2 + 1], afr, bfr[2], bfr[3]);
            }
        }

        // ---- online softmax (MUFU exp) ----
        float mx0 = -1e30f, mx1 = -1e30f;
        #pragma unroll
        for (int j = 0; j < 8; j++) {
            mx0 = fmaxf(mx0, fmaxf(sc[j][0], sc[j][1]));
            mx1 = fmaxf(mx1, fmaxf(sc[j][2], sc[j][3]));
        }
        #pragma unroll
        for (int ofs = 1; ofs <= 2; ofs <<= 1) {
            mx0 = fmaxf(mx0, __shfl_xor_sync(0xffffffffu, mx0, ofs));
            mx1 = fmaxf(mx1, __shfl_xor_sync(0xffffffffu, mx1, ofs));
        }
        float mn0 = fmaxf(mrow[0], mx0), mn1 = fmaxf(mrow[1], mx1);
        float corr0 = __expf(mrow[0] - mn0), corr1 = __expf(mrow[1] - mn1);
        mrow[0] = mn0; mrow[1] = mn1;

        float sum0 = 0.f, sum1 = 0.f;
        #pragma unroll
        for (int j = 0; j < 8; j++) {
            sc[j][0] = __expf(sc[j][0] - mn0);
            sc[j][1] = __expf(sc[j][1] - mn0);
            sc[j][2] = __expf(sc[j][2] - mn1);
            sc[j][3] = __expf(sc[j][3] - mn1);
            sum0 += sc[j][0] + sc[j][1];
            sum1 += sc[j][2] + sc[j][3];
        }
        #pragma unroll
        for (int ofs = 1; ofs <= 2; ofs <<= 1) {
            sum0 += __shfl_xor_sync(0xffffffffu, sum0, ofs);
            sum1 += __shfl_xor_sync(0xffffffffu, sum1, ofs);
        }
        lrow[0] = lrow[0] * corr0 + sum0;
        lrow[1] = lrow[1] * corr1 + sum1;
        #pragma unroll
        for (int nd = 0; nd < 8; nd++) {
            o[nd][0] *= corr0; o[nd][1] *= corr0;
            o[nd][2] *= corr1; o[nd][3] *= corr1;
        }

        // ---- P frags (1-term bf16 RN) ----
        uint32_t ph[4][4];
        #pragma unroll
        for (int kc = 0; kc < 4; kc++) {
            int j0 = kc * 2, j1 = kc * 2 + 1;
            ph[kc][0] = pack_bf16(sc[j0][0], sc[j0][1]);
            ph[kc][1] = pack_bf16(sc[j0][2], sc[j0][3]);
            ph[kc][2] = pack_bf16(sc[j1][0], sc[j1][1]);
            ph[kc][3] = pack_bf16(sc[j1][2], sc[j1][3]);
        }

        // ---- O += P V (bf16 1-term) ----
        #pragma unroll
        for (int kc = 0; kc < 4; kc++) {
            #pragma unroll
            for (int np = 0; np < 4; np++) {
                uint32_t vhf[4];
                int row = kc * 16 + (lid & 7) + ((lid >> 3) & 1) * 8;
                int c16 = np * 2 + ((lid >> 4) & 1);
                ldmatrix_x4_trans(vhf, vbase + ((row * 128) + (((c16 ^ (row & 7)) & 7) << 4)));
                mma16816(o[np * 2 + 0], ph[kc], vhf[0], vhf[1]);
                mma16816(o[np * 2 + 1], ph[kc], vhf[2], vhf[3]);
            }
        }
        __syncthreads();
    }

    // ---- epilogue: normalize, write bf16 [m][E] ----
    float inv0 = 1.f / lrow[0], inv1 = 1.f / lrow[1];
    int b = bh >> 3, h = bh & 7;
    int r0 = lid >> 2, c0 = (lid & 3) * 2;
    #pragma unroll
    for (int nd = 0; nd < 8; nd++) {
        int col = h * HEAD_DIM + nd * 8 + c0;
        #pragma unroll
        for (int rr = 0; rr < 2; rr++) {
            int w = q0 + wid * 16 + r0 + rr * 8;
            int m = w * BSZ + b;
            float inv = rr ? inv1 : inv0;
            float vx = o[nd][rr * 2 + 0] * inv;
            float vy = o[nd][rr * 2 + 1] * inv;
            *(__nv_bfloat162*)&g_attnh[(size_t)m * EMBED + col] = __floats2bfloat162_rn(vx, vy);
        }
    }
}

// ---------------------------------------------------------------- launcher
extern "C" void kernel_launch(void* const* d_in, const int* in_sizes, int n_in,
                              void* d_out, int out_size) {
    const float* feat  = (const float*)d_in[0];
    const float* in_w  = (const float*)d_in[1];
    const float* in_b  = (const float*)d_in[2];
    const float* out_w = (const float*)d_in[3];
    const float* out_b = (const float*)d_in[4];
    const float* ln_g  = (const float*)d_in[5];
    const float* ln_b  = (const float*)d_in[6];
    float* out = (float*)d_out;

    __nv_bfloat16 *xh, *wh, *owh, *attnh;
    cudaGetSymbolAddress((void**)&xh,    g_xh);
    cudaGetSymbolAddress((void**)&wh,    g_wh);
    cudaGetSymbolAddress((void**)&owh,   g_owh);
    cudaGetSymbolAddress((void**)&attnh, g_attnh);

    cudaFuncSetAttribute(gemm_mma<1>, cudaFuncAttributeMaxDynamicSharedMemorySize, GEMM_SMEM);
    cudaFuncSetAttribute(gemm_mma<2>, cudaFuncAttributeMaxDynamicSharedMemorySize, GEMM_SMEM);
    cudaFuncSetAttribute(attn_kernel, cudaFuncAttributeMaxDynamicSharedMemorySize, ATTN_SMEM);

    // 1. LayerNorm -> bf16
    ln_kernel<<<M_ROWS, 256>>>(feat, ln_g, ln_b);

    // 2. weights -> bf16
    wconv_kernel<<<(QKV_N * EMBED + 255) / 256, 256>>>(in_w, wh, QKV_N * EMBED);
    wconv_kernel<<<(EMBED * EMBED + 255) / 256, 256>>>(out_w, owh, EMBED * EMBED);

    // 3. QKV projection (bf16 mma) -> q/k tf32 f32, v bf16 in [bh][w][d]
    gemm_mma<2><<<dim3(QKV_N / 128, M_ROWS / 128), 256, GEMM_SMEM>>>(
        xh, wh, in_b, nullptr, nullptr, QKV_N);

    // 4. Attention (tf32 QK, MUFU exp, bf16 1-term PV) -> bf16
    attn_kernel<<<dim3(W_LEN / 128, BSZ * NHEADS), 256, ATTN_SMEM>>>();

    // 5. Out projection (bf16 mma) + bias + residual -> d_out
    gemm_mma<1><<<dim3(EMBED / 128, M_ROWS / 128), 256, GEMM_SMEM>>>(
        attnh, owh, out_b, feat, out, EMBED);
}